// round 7
// baseline (speedup 1.0000x reference)
#include <cuda_runtime.h>
#include <cuda_bf16.h>
#include <stdint.h>
#include <math.h>

#define MB   2
#define SEQ  2048
#define DM   4096
#define NH   16
#define HDIM 256
#define ROTD 64

#define BK 64
#define NKT (DM / BK)       // 64 K-chunks
#define BLK_BYTES 16384     // one 128x64 bf16 tile, SW128-swizzled image

// ---------------- scratch ----------------
__device__ float g_V[(size_t)MB * NH * SEQ * HDIM];
__device__ float2 g_rope[(size_t)MB * SEQ * 32];

// tiled + swizzled bf16 operand images for GEMMs
__device__ __align__(1024) __nv_bfloat16 g_Xhi[(size_t)DM * DM];
__device__ __align__(1024) __nv_bfloat16 g_Xlo[(size_t)DM * DM];
__device__ __align__(1024) __nv_bfloat16 g_Chi[(size_t)DM * DM];
__device__ __align__(1024) __nv_bfloat16 g_Clo[(size_t)DM * DM];
__device__ __align__(1024) __nv_bfloat16 g_WThi[4][(size_t)DM * DM];
__device__ __align__(1024) __nv_bfloat16 g_WTlo[4][(size_t)DM * DM];

// attention packed operands
__device__ __align__(1024) __nv_bfloat16 g_Qph[(size_t)32 * 2048 * 256];
__device__ __align__(1024) __nv_bfloat16 g_Qpl[(size_t)32 * 2048 * 256];
__device__ __align__(1024) __nv_bfloat16 g_Kph[(size_t)32 * 2048 * 256];
__device__ __align__(1024) __nv_bfloat16 g_Kpl[(size_t)32 * 2048 * 256];
__device__ __align__(1024) __nv_bfloat16 g_Vph[(size_t)32 * 2048 * 256];
__device__ __align__(1024) __nv_bfloat16 g_Vpl[(size_t)32 * 2048 * 256];

// ---------------- helpers ----------------
__device__ __forceinline__ uint32_t smem_to_u32(const void* p) {
    uint32_t a;
    asm("{ .reg .u64 t; cvta.to.shared.u64 t, %1; cvt.u32.u64 %0, t; }" : "=r"(a) : "l"(p));
    return a;
}
#define MBARRIER_INIT(a, c) \
    asm volatile("mbarrier.init.shared.b64 [%0], %1;" :: "r"((uint32_t)(a)), "r"((uint32_t)(c)) : "memory")
#define MBARRIER_EXPECT_TX(a, tx) \
    asm volatile("mbarrier.arrive.expect_tx.shared.b64 _, [%0], %1;" :: "r"((uint32_t)(a)), "r"((uint32_t)(tx)) : "memory")
#define MBARRIER_ARRIVE(a) \
    asm volatile("mbarrier.arrive.shared.b64 _, [%0];" :: "r"((uint32_t)(a)) : "memory")
#define FENCE_PROXY_ASYNC() asm volatile("fence.proxy.async.shared::cta;" ::: "memory")
#define MBARRIER_WAIT_PARITY(mbar_smem_addr, phase_parity) do { \
    uint32_t _mbar = (uint32_t)(mbar_smem_addr); \
    uint32_t _parity = (uint32_t)(phase_parity); \
    uint32_t _done; \
    asm volatile("{\n\t.reg .pred p;\n\t" \
        "mbarrier.try_wait.parity.acquire.cta.shared::cta.b64 p, [%1], %2;\n\t" \
        "selp.b32 %0, 1, 0, p;\n\t}" \
        : "=r"(_done) : "r"(_mbar), "r"(_parity) : "memory"); \
    if (!_done) { \
        asm volatile("{\n\t.reg .pred P1;\n\t" \
            "WAIT_LOOP_%=:\n\t" \
            "mbarrier.try_wait.parity.acquire.cta.shared::cta.b64 P1, [%0], %1, 0x989680;\n\t" \
            "@P1 bra.uni WAIT_DONE_%=;\n\t" \
            "bra.uni WAIT_LOOP_%=;\n\t" \
            "WAIT_DONE_%=:\n\t}" \
            :: "r"(_mbar), "r"(_parity) : "memory"); \
    } \
} while(0)

__device__ __forceinline__ void tma_bulk(uint32_t dst, const void* src, uint32_t bytes, uint32_t mbar) {
    asm volatile("cp.async.bulk.shared::cluster.global.mbarrier::complete_tx::bytes [%0], [%1], %2, [%3];"
        :: "r"(dst), "l"(src), "r"(bytes), "r"(mbar) : "memory");
}

#define SMEM_SWIZZLE_128B(x) ((x) ^ (((x) >> 3) & 0x70))
__device__ __forceinline__ uint32_t swz64(int r, int c) {
    return (uint32_t)(r * 64 + ((c ^ ((r >> 1) & 3)) << 4));
}

#define LDSM4(r, addr) \
    asm volatile("ldmatrix.sync.aligned.m8n8.x4.shared.b16 {%0,%1,%2,%3}, [%4];" \
        : "=r"((r)[0]), "=r"((r)[1]), "=r"((r)[2]), "=r"((r)[3]) : "r"(addr))

__device__ __forceinline__ void mma16816(float* c, const uint32_t* a, uint32_t b0, uint32_t b1) {
    asm volatile("mma.sync.aligned.m16n8k16.row.col.f32.bf16.bf16.f32 "
        "{%0,%1,%2,%3}, {%4,%5,%6,%7}, {%8,%9}, {%0,%1,%2,%3};"
        : "+f"(c[0]), "+f"(c[1]), "+f"(c[2]), "+f"(c[3])
        : "r"(a[0]), "r"(a[1]), "r"(a[2]), "r"(a[3]), "r"(b0), "r"(b1));
}

__device__ __forceinline__ float ex2(float x) {
    float r;
    asm("ex2.approx.f32 %0, %1;" : "=f"(r) : "f"(x));
    return r;
}

__device__ __forceinline__ void split1(float v, __nv_bfloat16& h, __nv_bfloat16& l) {
    h = __float2bfloat16(v);
    l = __float2bfloat16(v - __bfloat162float(h));
}
__device__ __forceinline__ uint32_t pk2(float a, float b) {
    __nv_bfloat162 t = __floats2bfloat162_rn(a, b);
    return *(uint32_t*)&t;
}
__device__ __forceinline__ void pksplit2(float a, float b, uint32_t& hi, uint32_t& lo) {
    __nv_bfloat16 ah = __float2bfloat16(a), bh = __float2bfloat16(b);
    __nv_bfloat162 hp; hp.x = ah; hp.y = bh;
    hi = *(uint32_t*)&hp;
    lo = pk2(a - __bfloat162float(ah), b - __bfloat162float(bh));
}

// ---------------------------------------------------------------------------
// rope table
// ---------------------------------------------------------------------------
__global__ void __launch_bounds__(256) rope_tab(const int* __restrict__ pos, float2* __restrict__ tab)
{
    int idx = blockIdx.x * 256 + threadIdx.x;
    if (idx >= MB * SEQ * 32) return;
    int i = idx & 31, s = (idx >> 5) & (SEQ - 1), b = idx >> 16;
    int p = pos[b * SEQ + s];
    double inv = pow(10000.0, -(double)(2 * i) / (double)ROTD);
    double sn, cs;
    sincos((double)p * inv, &sn, &cs);
    tab[idx] = make_float2((float)cs, (float)sn);
}

// ---------------------------------------------------------------------------
// split fp32 row-major -> tiled+swizzled bf16 hi/lo blocks (GEMM A)
// ---------------------------------------------------------------------------
__global__ void __launch_bounds__(256) split_rm_tiled(const float* __restrict__ in,
                                                      __nv_bfloat16* __restrict__ hi,
                                                      __nv_bfloat16* __restrict__ lo)
{
    size_t idx = (size_t)blockIdx.x * 256 + threadIdx.x;
    int m  = (int)(idx >> 9);
    int k  = (int)(idx & 511) << 3;
    const float4* p = (const float4*)(in + ((size_t)m << 12) + k);
    float4 v0 = p[0], v1 = p[1];

    __nv_bfloat16 h[8], l[8];
    split1(v0.x, h[0], l[0]); split1(v0.y, h[1], l[1]);
    split1(v0.z, h[2], l[2]); split1(v0.w, h[3], l[3]);
    split1(v1.x, h[4], l[4]); split1(v1.y, h[5], l[5]);
    split1(v1.z, h[6], l[6]); split1(v1.w, h[7], l[7]);

    int mt = m >> 7, r = m & 127, kt = k >> 6, c = k & 63;
    size_t base = ((size_t)mt * NKT + kt) * BLK_BYTES
                + SMEM_SWIZZLE_128B((uint32_t)(r * 128 + c * 2));
    *(uint4*)((char*)hi + base) = *(uint4*)h;
    *(uint4*)((char*)lo + base) = *(uint4*)l;
}

// ---------------------------------------------------------------------------
// W [K][N] fp32 -> BT tiled+swizzled bf16 hi/lo (transpose + split)
// ---------------------------------------------------------------------------
__global__ void __launch_bounds__(256) split_tr_tiled(const float* __restrict__ W,
                                                      __nv_bfloat16* __restrict__ Thi,
                                                      __nv_bfloat16* __restrict__ Tlo)
{
    __shared__ float t[32][33];
    int w = threadIdx.x;
    int nb = blockIdx.x * 32, kb = blockIdx.y * 32;
    int tx = w & 31, ty = w >> 5;
#pragma unroll
    for (int j = 0; j < 4; j++)
        t[ty + j * 8][tx] = W[(size_t)(kb + ty + j * 8) * DM + nb + tx];
    __syncthreads();

    int half = w >> 7, w7 = w & 127;
    int nn = w7 >> 2, kc = (w7 & 3) * 8;
    int n = nb + nn, kk = kb + kc;
    float v[8];
#pragma unroll
    for (int q = 0; q < 8; q++) v[q] = t[kc + q][nn];

    int nt = n >> 7, r = n & 127, kt = kk >> 6, c = kk & 63;
    size_t base = ((size_t)nt * NKT + kt) * BLK_BYTES
                + SMEM_SWIZZLE_128B((uint32_t)(r * 128 + c * 2));
    __nv_bfloat16 o[8];
    if (half == 0) {
#pragma unroll
        for (int q = 0; q < 8; q++) o[q] = __float2bfloat16(v[q]);
        *(uint4*)((char*)Thi + base) = *(uint4*)o;
    } else {
#pragma unroll
        for (int q = 0; q < 8; q++) {
            __nv_bfloat16 hh = __float2bfloat16(v[q]);
            o[q] = __float2bfloat16(v[q] - __bfloat162float(hh));
        }
        *(uint4*)((char*)Tlo + base) = *(uint4*)o;
    }
}

// ---------------------------------------------------------------------------
// HMMA split-bf16 GEMM, 128x128 CTA tile, 64x32 warp tile (2M x 4N warps),
// 3-stage TMA pipeline + double-buffered register fragments.
// stage (64KB): Ah 16KB, Al 16KB, Bh 16KB, Bl 16KB
// mode 0: fp32 row-major -> Cf. mode 1: tsel = global_n>>12:
//   0: rope+split -> packed Q; 1: -> packed K; 2: fp32 scatter [B,H,S,HD] -> Cf
// ---------------------------------------------------------------------------

#define LOADFR(S, ST, KS) do { \
    _Pragma("unroll") \
    for (int im_ = 0; im_ < 4; im_++) { \
        uint32_t off_ = SMEM_SWIZZLE_128B((uint32_t)((wm * 64 + im_ * 16 + ra) * 128 + (KS) * 32 + ca)); \
        LDSM4(fah##S[im_], (ST) + off_); \
        LDSM4(fal##S[im_], (ST) + 16384u + off_); \
    } \
    _Pragma("unroll") \
    for (int ip_ = 0; ip_ < 2; ip_++) { \
        uint32_t off_ = SMEM_SWIZZLE_128B((uint32_t)((wn * 32 + ip_ * 16 + rb) * 128 + (KS) * 32 + cb)); \
        LDSM4(fbh##S[ip_], (ST) + 32768u + off_); \
        LDSM4(fbl##S[ip_], (ST) + 49152u + off_); \
    } \
} while (0)

#define MMAS(S) do { \
    _Pragma("unroll") \
    for (int im_ = 0; im_ < 4; im_++) \
    _Pragma("unroll") \
    for (int in_ = 0; in_ < 4; in_++) { \
        const int ip_ = in_ >> 1, sel_ = in_ & 1; \
        mma16816(acc[im_][in_], fah##S[im_], fbh##S[ip_][sel_], fbh##S[ip_][sel_ + 2]); \
        mma16816(acc[im_][in_], fah##S[im_], fbl##S[ip_][sel_], fbl##S[ip_][sel_ + 2]); \
        mma16816(acc[im_][in_], fal##S[im_], fbh##S[ip_][sel_], fbh##S[ip_][sel_ + 2]); \
    } \
} while (0)

__global__ void __launch_bounds__(256, 1) gemm_hmma(
    const __nv_bfloat16* __restrict__ Ahi, const __nv_bfloat16* __restrict__ Alo,
    const __nv_bfloat16* __restrict__ Bhi, const __nv_bfloat16* __restrict__ Blo,
    float* __restrict__ Cf,
    __nv_bfloat16* __restrict__ Qh, __nv_bfloat16* __restrict__ Ql,
    __nv_bfloat16* __restrict__ Kh, __nv_bfloat16* __restrict__ Kl,
    const float2* __restrict__ rope, int mode)
{
    extern __shared__ char gsm[];
    uint32_t sb = (smem_to_u32(gsm) + 1023u) & ~1023u;
    const uint32_t stage0 = sb + 1024u;                   // 3 stages x 64KB
    const int tid = threadIdx.x, wid = tid >> 5, lane = tid & 31;
    const int bm = blockIdx.y * 128;
    const int bn_g = blockIdx.x * 128;
    const int wm = wid >> 2, wn = wid & 3;                // 2(M) x 4(N)

    if (tid == 0) {
#pragma unroll
        for (int s = 0; s < 3; s++) {
            MBARRIER_INIT(sb + s * 8, 1);          // full
            MBARRIER_INIT(sb + 24 + s * 8, 256);   // empty
        }
        FENCE_PROXY_ASYNC();
    }
    __syncthreads();

    const char* pAh = (const char*)Ahi + (((size_t)blockIdx.y * NKT) << 14);
    const char* pAl = (const char*)Alo + (((size_t)blockIdx.y * NKT) << 14);
    const char* pBh = (const char*)Bhi + (((size_t)blockIdx.x * NKT) << 14);
    const char* pBl = (const char*)Blo + (((size_t)blockIdx.x * NKT) << 14);

    auto issue = [&](int j) {
        const int s = j % 3;
        const uint32_t st = stage0 + (uint32_t)s * 65536u;
        const uint32_t mb = sb + (uint32_t)s * 8u;
        const size_t off = (size_t)j << 14;
        MBARRIER_EXPECT_TX(mb, 65536u);
        tma_bulk(st,           pAh + off, 16384u, mb);
        tma_bulk(st + 16384u,  pAl + off, 16384u, mb);
        tma_bulk(st + 32768u,  pBh + off, 16384u, mb);
        tma_bulk(st + 49152u,  pBl + off, 16384u, mb);
    };
    if (tid == 0) { issue(0); issue(1); issue(2); }

    float acc[4][4][4];
#pragma unroll
    for (int im = 0; im < 4; im++)
#pragma unroll
        for (int in = 0; in < 4; in++)
#pragma unroll
            for (int j = 0; j < 4; j++) acc[im][in][j] = 0.f;

    const int ra = lane & 15, ca = (lane >> 4) * 16;
    const int rb = (lane & 7) + 8 * ((lane >> 3) & 1), cb = (lane >> 4) * 16;

    uint32_t fah0[4][4], fal0[4][4], fbh0[2][4], fbl0[2][4];
    uint32_t fah1[4][4], fal1[4][4], fbh1[2][4], fbl1[2][4];

    uint32_t fphb = 0u, ephb = 0u;
    MBARRIER_WAIT_PARITY(sb, 0);
    fphb = 1u;
    LOADFR(0, stage0, 0);

    for (int kp = 0; kp < 128; kp++) {
        const int k0 = kp * 2, k1 = k0 + 1;
        // half A: prefetch frags for k1 (same chunk, odd ks), compute k0
        {
            const int nc = k1 >> 2, ns = nc % 3;
            const uint32_t nst = stage0 + (uint32_t)ns * 65536u;
            LOADFR(1, nst, k1 & 3);
            if ((k1 & 3) == 3) {
                MBARRIER_ARRIVE(sb + 24 + ns * 8);
                if (tid == 0) {
                    const int nxt = nc + 3;
                    if (nxt < NKT) {
                        MBARRIER_WAIT_PARITY(sb + 24 + ns * 8, (ephb >> ns) & 1u);
                        ephb ^= (1u << ns);
                        issue(nxt);
                    }
                }
            }
            MMAS(0);
        }
        // half B: prefetch frags for k2 (may cross chunk), compute k1
        {
            const int k2 = k0 + 2;
            if (k2 < 256) {
                const int nc = k2 >> 2, ns = nc % 3;
                const uint32_t nst = stage0 + (uint32_t)ns * 65536u;
                if ((k2 & 3) == 0) {
                    MBARRIER_WAIT_PARITY(sb + ns * 8, (fphb >> ns) & 1u);
                    fphb ^= (1u << ns);
                }
                LOADFR(0, nst, k2 & 3);
            }
            MMAS(1);
        }
    }

    // ---- epilogue ----
    const int tsel = bn_g >> 12;
    const int bn = bn_g & 4095;
#pragma unroll
    for (int im = 0; im < 4; im++) {
#pragma unroll
        for (int in = 0; in < 4; in++) {
            const float* c = acc[im][in];
            int m0 = bm + wm * 64 + im * 16 + (lane >> 2);
            int n  = bn + wn * 32 + in * 8 + (lane & 3) * 2;
#pragma unroll
            for (int half = 0; half < 2; half++) {
                int m = m0 + half * 8;
                float x = c[half * 2], y = c[half * 2 + 1];
                if (mode == 0) {
                    *(float2*)(Cf + (size_t)m * DM + n) = make_float2(x, y);
                } else {
                    int b = m >> 11, sq = m & 2047, h = n >> 8, hd = n & 255;
                    if (tsel == 2) {
                        *(float2*)(Cf + ((size_t)(b * NH + h) * SEQ + sq) * HDIM + hd)
                            = make_float2(x, y);
                    } else {
                        if (hd < ROTD) {
                            float2 t = rope[(size_t)(b * SEQ + sq) * 32 + (hd >> 1)];
                            float nx = x * t.x - y * t.y;
                            float ny = y * t.x + x * t.y;
                            x = nx; y = ny;
                        }
                        uint32_t hi, lo;
                        pksplit2(x, y, hi, lo);
                        int bh2 = b * NH + h, stq = sq >> 5, r = sq & 31;
                        int ct = hd >> 6, cc = hd & 63;
                        size_t dst = (((size_t)(bh2 * 64 + stq) * 4 + ct) << 12)
                                   + SMEM_SWIZZLE_128B((uint32_t)(r * 128 + cc * 2));
                        if (tsel == 0) {
                            *(uint32_t*)((char*)Qh + dst) = hi;
                            *(uint32_t*)((char*)Ql + dst) = lo;
                        } else {
                            *(uint32_t*)((char*)Kh + dst) = hi;
                            *(uint32_t*)((char*)Kl + dst) = lo;
                        }
                    }
                }
            }
        }
    }
}

// ---------------------------------------------------------------------------
// pack V transposed: fp32 [B,H,S,HD] -> Vt bf16 hi/lo
// ---------------------------------------------------------------------------
__global__ void __launch_bounds__(256) pack_v(const float* __restrict__ V,
                                              __nv_bfloat16* __restrict__ Vh, __nv_bfloat16* __restrict__ Vl)
{
    __shared__ float sm[32][257];
    int jt = blockIdx.x, bh = blockIdx.y;
    int t = threadIdx.x;
    int r = t >> 3, d0 = (t & 7) * 32;
    const float* src = V + ((size_t)bh * SEQ + jt * 32 + r) * HDIM + d0;
#pragma unroll
    for (int i = 0; i < 8; i++) {
        float4 v = *(const float4*)(src + i * 4);
        sm[r][d0 + i * 4 + 0] = v.x; sm[r][d0 + i * 4 + 1] = v.y;
        sm[r][d0 + i * 4 + 2] = v.z; sm[r][d0 + i * 4 + 3] = v.w;
    }
    __syncthreads();

    int d = t;
    int dt = d >> 7, rd = d & 127;
    size_t base = ((size_t)(bh * 64 + jt) * 2 + dt) << 13;
#pragma unroll
    for (int c = 0; c < 4; c++) {
        __nv_bfloat16 h[8], l[8];
#pragma unroll
        for (int jj = 0; jj < 8; jj++) split1(sm[c * 8 + jj][d], h[jj], l[jj]);
        size_t off = base + swz64(rd, c);
        *(uint4*)((char*)Vh + off) = *(uint4*)h;
        *(uint4*)((char*)Vl + off) = *(uint4*)l;
    }
}

// ---------------------------------------------------------------------------
// HMMA causal flash attention, split-bf16, online softmax.
// ---------------------------------------------------------------------------
__global__ void __launch_bounds__(128, 1) attn_mma(
    const __nv_bfloat16* __restrict__ Qph, const __nv_bfloat16* __restrict__ Qpl,
    const __nv_bfloat16* __restrict__ Kph, const __nv_bfloat16* __restrict__ Kpl,
    const __nv_bfloat16* __restrict__ Vph, const __nv_bfloat16* __restrict__ Vpl,
    __nv_bfloat16* __restrict__ Chi, __nv_bfloat16* __restrict__ Clo)
{
    extern __shared__ char gsm[];
    uint32_t sb = (smem_to_u32(gsm) + 1023u) & ~1023u;
    const uint32_t sq = sb + 1024u;
    const uint32_t sv = sq + 65536u;

    const int qt = (int)gridDim.x - 1 - (int)blockIdx.x;
    const int bh = blockIdx.y;
    const int b  = bh >> 4, h = bh & 15;
    const int tid = threadIdx.x, w = tid >> 5, lane = tid & 31;
    const int nkt = 2 * qt + 2;

    if (tid == 0) {
        MBARRIER_INIT(sb, 1);
        MBARRIER_INIT(sb + 8, 1);
        MBARRIER_INIT(sb + 16, 1);
        MBARRIER_INIT(sb + 24, 128);
        MBARRIER_INIT(sb + 32, 128);
        FENCE_PROXY_ASYNC();
    }
    __syncthreads();

    auto issueKV = [&](int kt, int s) {
        const uint32_t st = sv + (uint32_t)s * 65536u;
        const uint32_t mb = sb + 8 + (uint32_t)s * 8u;
        MBARRIER_EXPECT_TX(mb, 65536u);
        size_t kbase = ((size_t)(bh * 64 + kt) * 4) << 12;
#pragma unroll
        for (int ct = 0; ct < 4; ct++) {
            tma_bulk(st + ct * 4096,          (const char*)Kph + kbase + ct * 4096, 4096u, mb);
            tma_bulk(st + 16384 + ct * 4096,  (const char*)Kpl + kbase + ct * 4096, 4096u, mb);
        }
        size_t vbase = ((size_t)(bh * 64 + kt) * 2) << 13;
#pragma unroll
        for (int dt = 0; dt < 2; dt++) {
            tma_bulk(st + 32768 + dt * 8192,  (const char*)Vph + vbase + dt * 8192, 8192u, mb);
            tma_bulk(st + 49152 + dt * 8192,  (const char*)Vpl + vbase + dt * 8192, 8192u, mb);
        }
    };

    if (tid == 0) {
        MBARRIER_EXPECT_TX(sb, 65536u);
#pragma unroll
        for (int sb2 = 0; sb2 < 2; sb2++) {
            size_t qbase = ((size_t)(bh * 64 + qt * 2 + sb2) * 4) << 12;
#pragma unroll
            for (int ct = 0; ct < 4; ct++) {
                tma_bulk(sq + (sb2 * 4 + ct) * 4096,          (const char*)Qph + qbase + ct * 4096, 4096u, sb);
                tma_bulk(sq + 32768 + (sb2 * 4 + ct) * 4096,  (const char*)Qpl + qbase + ct * 4096, 4096u, sb);
            }
        }
        issueKV(0, 0);
        issueKV(1, 1);
    }

    float out[32][4];
#pragma unroll
    for (int i = 0; i < 32; i++)
#pragma unroll
        for (int j = 0; j < 4; j++) out[i][j] = 0.f;
    float m0 = -1e30f, m1 = -1e30f, l0 = 0.f, l1 = 0.f;

    const int ra = lane & 15;
    const int rb = (lane & 7) + 8 * ((lane >> 3) & 1);
    const int qrow = (w & 1) * 16 + ra;
    const int row0g = qt * 64 + w * 16 + (lane >> 2);
    const int row1g = row0g + 8;
    const float SC = 0.0901699438f;

    MBARRIER_WAIT_PARITY(sb, 0);

    int fph0 = 0, fph1 = 0, eph0 = 0, eph1 = 0;
    for (int kt = 0; kt < nkt; kt++) {
        const int s = kt & 1;
        const uint32_t st = sv + (uint32_t)s * 65536u;
        if (s == 0) { MBARRIER_WAIT_PARITY(sb + 8, fph0);  fph0 ^= 1; }
        else        { MBARRIER_WAIT_PARITY(sb + 16, fph1); fph1 ^= 1; }

        float sc[4][4];
#pragma unroll
        for (int f = 0; f < 4; f++)
#pragma unroll
            for (int j = 0; j < 4; j++) sc[f][j] = 0.f;

#pragma unroll
        for (int kk = 0; kk < 16; kk++) {
            uint32_t ah[4], al[4], kh[2][4], kl[2][4];
            uint32_t aoff = (uint32_t)(((w >> 1) * 4 + (kk >> 2)) * 4096)
                          + SMEM_SWIZZLE_128B((uint32_t)(qrow * 128 + (kk & 3) * 32 + (lane >> 4) * 16));
            LDSM4(ah, sq + aoff);
            LDSM4(al, sq + 32768u + aoff);
#pragma unroll
            for (int ip = 0; ip < 2; ip++) {
                uint32_t koff = (uint32_t)((kk >> 2) * 4096)
                              + SMEM_SWIZZLE_128B((uint32_t)((ip * 16 + rb) * 128 + (kk & 3) * 32 + (lane >> 4) * 16));
                LDSM4(kh[ip], st + koff);
                LDSM4(kl[ip], st + 16384u + koff);
            }
#pragma unroll
            for (int f = 0; f < 4; f++) {
                const int ip = f >> 1, sel = f & 1;
                mma16816(sc[f], ah, kh[ip][sel], kh[ip][sel + 2]);
                mma16816(sc[f], ah, kl[ip][sel], kl[ip][sel + 2]);
                mma16816(sc[f], al, kh[ip][sel], kh[ip][sel + 2]);
            }
        }

        const bool domask = (kt * 32 + 31) > (qt * 64 + w * 16);
        float tm0 = -1e30f, tm1 = -1e30f;
#pragma unroll
        for (int f = 0; f < 4; f++) {
#pragma unroll
            for (int j = 0; j < 4; j++) {
                float v = sc[f][j] * SC;
                if (domask) {
                    int col = kt * 32 + f * 8 + (lane & 3) * 2 + (j & 1);
                    int row = (j < 2) ? row0g : row1g;
                    if (col > row) v = -1e30f;
                }
                sc[f][j] = v;
                if (j < 2) tm0 = fmaxf(tm0, v); else tm1 = fmaxf(tm1, v);
            }
        }
        tm0 = fmaxf(tm0, __shfl_xor_sync(0xffffffffu, tm0, 1));
        tm0 = fmaxf(tm0, __shfl_xor_sync(0xffffffffu, tm0, 2));
        tm1 = fmaxf(tm1, __shfl_xor_sync(0xffffffffu, tm1, 1));
        tm1 = fmaxf(tm1, __shfl_xor_sync(0xffffffffu, tm1, 2));
        float nm0 = fmaxf(m0, tm0), nm1 = fmaxf(m1, tm1);
        float a0 = ex2(m0 - nm0), a1 = ex2(m1 - nm1);
        float ls0 = 0.f, ls1 = 0.f;
#pragma unroll
        for (int f = 0; f < 4; f++) {
            sc[f][0] = ex2(sc[f][0] - nm0); ls0 += sc[f][0];
            sc[f][1] = ex2(sc[f][1] - nm0); ls0 += sc[f][1];
            sc[f][2] = ex2(sc[f][2] - nm1); ls1 += sc[f][2];
            sc[f][3] = ex2(sc[f][3] - nm1); ls1 += sc[f][3];
        }
        ls0 += __shfl_xor_sync(0xffffffffu, ls0, 1);
        ls0 += __shfl_xor_sync(0xffffffffu, ls0, 2);
        ls1 += __shfl_xor_sync(0xffffffffu, ls1, 1);
        ls1 += __shfl_xor_sync(0xffffffffu, ls1, 2);
        l0 = l0 * a0 + ls0; l1 = l1 * a1 + ls1;
        m0 = nm0; m1 = nm1;

#pragma unroll
        for (int i = 0; i < 32; i++) {
            out[i][0] *= a0; out[i][1] *= a0;
            out[i][2] *= a1; out[i][3] *= a1;
        }

        uint32_t pah[2][4], pal[2][4];
#pragma unroll
        for (int kc = 0; kc < 2; kc++) {
            float* f0 = sc[2 * kc];
            float* f1 = sc[2 * kc + 1];
            pksplit2(f0[0], f0[1], pah[kc][0], pal[kc][0]);
            pksplit2(f0[2], f0[3], pah[kc][1], pal[kc][1]);
            pksplit2(f1[0], f1[1], pah[kc][2], pal[kc][2]);
            pksplit2(f1[2], f1[3], pah[kc][3], pal[kc][3]);
        }

#pragma unroll
        for (int kc = 0; kc < 2; kc++) {
#pragma unroll
            for (int dp = 0; dp < 16; dp++) {
                uint32_t vh[4], vl[4];
                int rr = (dp & 7) * 16 + rb;
                uint32_t voff = (uint32_t)((dp >> 3) * 8192) + swz64(rr, kc * 2 + (lane >> 4));
                LDSM4(vh, st + 32768u + voff);
                LDSM4(vl, st + 49152u + voff);
#pragma unroll
                for (int sel = 0; sel < 2; sel++) {
                    float* c = out[2 * dp + sel];
                    mma16816(c, pah[kc], vh[sel], vh[sel + 2]);
                    mma16816(c, pah[kc], vl[sel], vl[sel + 2]);
                    mma16816(c, pal[kc], vh[sel], vh[sel + 2]);
                }
            }
        }

        MBARRIER_ARRIVE(sb + 24 + s * 8);
        if (tid == 0 && kt + 2 < nkt) {
            if (s == 0) { MBARRIER_WAIT_PARITY(sb + 24, eph0); eph0 ^= 1; }
            else        { MBARRIER_WAIT_PARITY(sb + 32, eph1); eph1 ^= 1; }
            issueKV(kt + 2, s);
        }
    }

    // ---- epilogue: write packed GEMM-A tiles (Chi/Clo) directly ----
    float inv0 = 1.0f / l0, inv1 = 1.0f / l1;
    int mrow0 = b * SEQ + row0g;
    int mrow1 = b * SEQ + row1g;
    int mt0 = mrow0 >> 7, r0 = mrow0 & 127;
    int mt1 = mrow1 >> 7, r1 = mrow1 & 127;
#pragma unroll
    for (int nf = 0; nf < 32; nf++) {
        int d = h * HDIM + nf * 8 + (lane & 3) * 2;
        int ktb = d >> 6, cc = d & 63;
        uint32_t hi, lo;
        pksplit2(out[nf][0] * inv0, out[nf][1] * inv0, hi, lo);
        size_t a0a = (((size_t)mt0 * NKT + ktb) << 14)
                   + SMEM_SWIZZLE_128B((uint32_t)(r0 * 128 + cc * 2));
        *(uint32_t*)((char*)Chi + a0a) = hi;
        *(uint32_t*)((char*)Clo + a0a) = lo;
        pksplit2(out[nf][2] * inv1, out[nf][3] * inv1, hi, lo);
        size_t a1a = (((size_t)mt1 * NKT + ktb) << 14)
                   + SMEM_SWIZZLE_128B((uint32_t)(r1 * 128 + cc * 2));
        *(uint32_t*)((char*)Chi + a1a) = hi;
        *(uint32_t*)((char*)Clo + a1a) = lo;
    }
}

// ---------------------------------------------------------------------------
extern "C" void kernel_launch(void* const* d_in, const int* in_sizes, int n_in,
                              void* d_out, int out_size)
{
    const float* X   = (const float*)d_in[0];
    const int*   pos = (const int*)  d_in[1];
    const float* W[4] = { (const float*)d_in[2], (const float*)d_in[3],
                          (const float*)d_in[4], (const float*)d_in[5] };
    float* out = (float*)d_out;

    float *Vg;
    float2* rope;
    __nv_bfloat16 *Xhi, *Xlo, *Chi, *Clo, *WThi, *WTlo;
    __nv_bfloat16 *Qph, *Qpl, *Kph, *Kpl, *Vph, *Vpl;
    cudaGetSymbolAddress((void**)&Vg,  g_V);
    cudaGetSymbolAddress((void**)&rope, g_rope);
    cudaGetSymbolAddress((void**)&Xhi, g_Xhi);
    cudaGetSymbolAddress((void**)&Xlo, g_Xlo);
    cudaGetSymbolAddress((void**)&Chi, g_Chi);
    cudaGetSymbolAddress((void**)&Clo, g_Clo);
    cudaGetSymbolAddress((void**)&WThi, g_WThi);
    cudaGetSymbolAddress((void**)&WTlo, g_WTlo);
    cudaGetSymbolAddress((void**)&Qph, g_Qph);
    cudaGetSymbolAddress((void**)&Qpl, g_Qpl);
    cudaGetSymbolAddress((void**)&Kph, g_Kph);
    cudaGetSymbolAddress((void**)&Kpl, g_Kpl);
    cudaGetSymbolAddress((void**)&Vph, g_Vph);
    cudaGetSymbolAddress((void**)&Vpl, g_Vpl);

    const int GEMM_SMEM = 1024 + 1024 + 3 * 65536;          // 198656
    const int ATTN_SMEM = 1024 + 1024 + 65536 + 2 * 65536;  // 198656
    cudaFuncSetAttribute(gemm_hmma, cudaFuncAttributeMaxDynamicSharedMemorySize, GEMM_SMEM);
    cudaFuncSetAttribute(attn_mma, cudaFuncAttributeMaxDynamicSharedMemorySize, ATTN_SMEM);

    const size_t WSZ = (size_t)DM * DM;
    dim3 trg(DM / 32, DM / 32);

    // launch order chosen so ncu (-s 5 -c 1) captures the QKV GEMM (6th launch)
    split_rm_tiled<<<8192, 256>>>(X, Xhi, Xlo);                                   // 1
    split_tr_tiled<<<trg, 256>>>(W[0], WThi + 0 * WSZ, WTlo + 0 * WSZ);           // 2
    split_tr_tiled<<<trg, 256>>>(W[1], WThi + 1 * WSZ, WTlo + 1 * WSZ);           // 3
    split_tr_tiled<<<trg, 256>>>(W[2], WThi + 2 * WSZ, WTlo + 2 * WSZ);           // 4
    rope_tab<<<(MB * SEQ * 32 + 255) / 256, 256>>>(pos, rope);                    // 5

    // fused QKV projection: rope + split packed in epilogue (Q,K); V fp32       // 6
    gemm_hmma<<<dim3(96, 32), 256, GEMM_SMEM>>>(Xhi, Xlo, WThi, WTlo,
                                                Vg, Qph, Qpl, Kph, Kpl, rope, 1);

    split_tr_tiled<<<trg, 256>>>(W[3], WThi + 3 * WSZ, WTlo + 3 * WSZ);           // 7
    pack_v<<<dim3(64, 32), 256>>>(Vg, Vph, Vpl);                                  // 8

    // attention (writes packed Chi/Clo)
    attn_mma<<<dim3(32, 32), 128, ATTN_SMEM>>>(Qph, Qpl, Kph, Kpl, Vph, Vpl, Chi, Clo);

    // output projection
    gemm_hmma<<<dim3(32, 32), 256, GEMM_SMEM>>>(Chi, Clo, WThi + 3 * WSZ, WTlo + 3 * WSZ,
                                                out, nullptr, nullptr, nullptr, nullptr,
                                                nullptr, 0);
}

// round 8
// speedup vs baseline: 1.1635x; 1.1635x over previous
#include <cuda_runtime.h>
#include <cuda_bf16.h>
#include <stdint.h>
#include <math.h>

#define MB   2
#define SEQ  2048
#define DM   4096
#define NH   16
#define HDIM 256
#define ROTD 64

#define BK 32
#define NKT2 128            // K-chunks of 32
#define BLK2 8192           // one 128x32 bf16 block, 64B-row swizzled

// ---------------- scratch ----------------
__device__ float g_Q[(size_t)MB * NH * SEQ * HDIM];
__device__ float g_K[(size_t)MB * NH * SEQ * HDIM];
__device__ float g_V[(size_t)MB * NH * SEQ * HDIM];
__device__ float g_CTX[(size_t)MB * SEQ * DM];

// tiled + swizzled bf16 operand images (128x32 blocks, 8KB each)
__device__ __align__(1024) __nv_bfloat16 g_Xhi[(size_t)DM * DM];
__device__ __align__(1024) __nv_bfloat16 g_Xlo[(size_t)DM * DM];
__device__ __align__(1024) __nv_bfloat16 g_Chi[(size_t)DM * DM];
__device__ __align__(1024) __nv_bfloat16 g_Clo[(size_t)DM * DM];
__device__ __align__(1024) __nv_bfloat16 g_WThi[4][(size_t)DM * DM];
__device__ __align__(1024) __nv_bfloat16 g_WTlo[4][(size_t)DM * DM];

// attention packed operands (layouts unchanged from round 4)
__device__ __align__(1024) __nv_bfloat16 g_Qph[(size_t)32 * 2048 * 256];
__device__ __align__(1024) __nv_bfloat16 g_Qpl[(size_t)32 * 2048 * 256];
__device__ __align__(1024) __nv_bfloat16 g_Kph[(size_t)32 * 2048 * 256];
__device__ __align__(1024) __nv_bfloat16 g_Kpl[(size_t)32 * 2048 * 256];
__device__ __align__(1024) __nv_bfloat16 g_Vph[(size_t)32 * 2048 * 256];
__device__ __align__(1024) __nv_bfloat16 g_Vpl[(size_t)32 * 2048 * 256];

// ---------------- helpers ----------------
__device__ __forceinline__ uint32_t smem_to_u32(const void* p) {
    uint32_t a;
    asm("{ .reg .u64 t; cvta.to.shared.u64 t, %1; cvt.u32.u64 %0, t; }" : "=r"(a) : "l"(p));
    return a;
}
#define MBARRIER_INIT(a, c) \
    asm volatile("mbarrier.init.shared.b64 [%0], %1;" :: "r"((uint32_t)(a)), "r"((uint32_t)(c)) : "memory")
#define MBARRIER_EXPECT_TX(a, tx) \
    asm volatile("mbarrier.arrive.expect_tx.shared.b64 _, [%0], %1;" :: "r"((uint32_t)(a)), "r"((uint32_t)(tx)) : "memory")
#define MBARRIER_ARRIVE(a) \
    asm volatile("mbarrier.arrive.shared.b64 _, [%0];" :: "r"((uint32_t)(a)) : "memory")
#define FENCE_PROXY_ASYNC() asm volatile("fence.proxy.async.shared::cta;" ::: "memory")
#define MBARRIER_WAIT_PARITY(mbar_smem_addr, phase_parity) do { \
    uint32_t _mbar = (uint32_t)(mbar_smem_addr); \
    uint32_t _parity = (uint32_t)(phase_parity); \
    uint32_t _done; \
    asm volatile("{\n\t.reg .pred p;\n\t" \
        "mbarrier.try_wait.parity.acquire.cta.shared::cta.b64 p, [%1], %2;\n\t" \
        "selp.b32 %0, 1, 0, p;\n\t}" \
        : "=r"(_done) : "r"(_mbar), "r"(_parity) : "memory"); \
    if (!_done) { \
        asm volatile("{\n\t.reg .pred P1;\n\t" \
            "WAIT_LOOP_%=:\n\t" \
            "mbarrier.try_wait.parity.acquire.cta.shared::cta.b64 P1, [%0], %1, 0x989680;\n\t" \
            "@P1 bra.uni WAIT_DONE_%=;\n\t" \
            "bra.uni WAIT_LOOP_%=;\n\t" \
            "WAIT_DONE_%=:\n\t}" \
            :: "r"(_mbar), "r"(_parity) : "memory"); \
    } \
} while(0)

__device__ __forceinline__ void tma_bulk(uint32_t dst, const void* src, uint32_t bytes, uint32_t mbar) {
    asm volatile("cp.async.bulk.shared::cluster.global.mbarrier::complete_tx::bytes [%0], [%1], %2, [%3];"
        :: "r"(dst), "l"(src), "r"(bytes), "r"(mbar) : "memory");
}

#define SMEM_SWIZZLE_128B(x) ((x) ^ (((x) >> 3) & 0x70))
// 64B-row swizzle: row r, 16B chunk c (0..3)
__device__ __forceinline__ uint32_t swz64(int r, int c) {
    return (uint32_t)(r * 64 + ((c ^ ((r >> 1) & 3)) << 4));
}

#define LDSM4(r, addr) \
    asm volatile("ldmatrix.sync.aligned.m8n8.x4.shared.b16 {%0,%1,%2,%3}, [%4];" \
        : "=r"((r)[0]), "=r"((r)[1]), "=r"((r)[2]), "=r"((r)[3]) : "r"(addr))

__device__ __forceinline__ void mma16816(float* c, const uint32_t* a, uint32_t b0, uint32_t b1) {
    asm volatile("mma.sync.aligned.m16n8k16.row.col.f32.bf16.bf16.f32 "
        "{%0,%1,%2,%3}, {%4,%5,%6,%7}, {%8,%9}, {%0,%1,%2,%3};"
        : "+f"(c[0]), "+f"(c[1]), "+f"(c[2]), "+f"(c[3])
        : "r"(a[0]), "r"(a[1]), "r"(a[2]), "r"(a[3]), "r"(b0), "r"(b1));
}

__device__ __forceinline__ float ex2(float x) {
    float r;
    asm("ex2.approx.f32 %0, %1;" : "=f"(r) : "f"(x));
    return r;
}

__device__ __forceinline__ void split1(float v, __nv_bfloat16& h, __nv_bfloat16& l) {
    h = __float2bfloat16(v);
    l = __float2bfloat16(v - __bfloat162float(h));
}
__device__ __forceinline__ uint32_t pk2(float a, float b) {
    __nv_bfloat162 t = __floats2bfloat162_rn(a, b);
    return *(uint32_t*)&t;
}
__device__ __forceinline__ void pksplit2(float a, float b, uint32_t& hi, uint32_t& lo) {
    __nv_bfloat16 ah = __float2bfloat16(a), bh = __float2bfloat16(b);
    __nv_bfloat162 hp; hp.x = ah; hp.y = bh;
    hi = *(uint32_t*)&hp;
    lo = pk2(a - __bfloat162float(ah), b - __bfloat162float(bh));
}

// ---------------------------------------------------------------------------
// split fp32 row-major [4096][4096] -> 128x32 blocks, 64B-row swizzle
// one thread per 8 consecutive K elements (one 16B chunk)
// ---------------------------------------------------------------------------
__global__ void __launch_bounds__(256) split_rm_tiled(const float* __restrict__ in,
                                                      __nv_bfloat16* __restrict__ hi,
                                                      __nv_bfloat16* __restrict__ lo)
{
    size_t idx = (size_t)blockIdx.x * 256 + threadIdx.x;
    int m  = (int)(idx >> 9);
    int k  = (int)(idx & 511) << 3;
    const float4* p = (const float4*)(in + ((size_t)m << 12) + k);
    float4 v0 = p[0], v1 = p[1];

    __nv_bfloat16 h[8], l[8];
    split1(v0.x, h[0], l[0]); split1(v0.y, h[1], l[1]);
    split1(v0.z, h[2], l[2]); split1(v0.w, h[3], l[3]);
    split1(v1.x, h[4], l[4]); split1(v1.y, h[5], l[5]);
    split1(v1.z, h[6], l[6]); split1(v1.w, h[7], l[7]);

    int mt = m >> 7, r = m & 127, kt = k >> 5, c = (k >> 3) & 3;
    size_t base = ((size_t)(mt * NKT2 + kt)) * BLK2 + swz64(r, c);
    *(uint4*)((char*)hi + base) = *(uint4*)h;
    *(uint4*)((char*)lo + base) = *(uint4*)l;
}

// ---------------------------------------------------------------------------
// W [K][N] fp32 -> BT 128x32 blocks, 64B-row swizzle (transpose + split)
// ---------------------------------------------------------------------------
__global__ void __launch_bounds__(256) split_tr_tiled(const float* __restrict__ W,
                                                      __nv_bfloat16* __restrict__ Thi,
                                                      __nv_bfloat16* __restrict__ Tlo)
{
    __shared__ float t[32][33];
    int w = threadIdx.x;
    int nb = blockIdx.x * 32, kb = blockIdx.y * 32;
    int tx = w & 31, ty = w >> 5;
#pragma unroll
    for (int j = 0; j < 4; j++)
        t[ty + j * 8][tx] = W[(size_t)(kb + ty + j * 8) * DM + nb + tx];
    __syncthreads();

    int half = w >> 7, w7 = w & 127;
    int nn = w7 >> 2, kc = (w7 & 3) * 8;
    int n = nb + nn, kk = kb + kc;
    float v[8];
#pragma unroll
    for (int q = 0; q < 8; q++) v[q] = t[kc + q][nn];

    int nt = n >> 7, r = n & 127, kt = kk >> 5, c = (kk >> 3) & 3;
    size_t base = ((size_t)(nt * NKT2 + kt)) * BLK2 + swz64(r, c);
    __nv_bfloat16 o[8];
    if (half == 0) {
#pragma unroll
        for (int q = 0; q < 8; q++) o[q] = __float2bfloat16(v[q]);
        *(uint4*)((char*)Thi + base) = *(uint4*)o;
    } else {
#pragma unroll
        for (int q = 0; q < 8; q++) {
            __nv_bfloat16 hh = __float2bfloat16(v[q]);
            o[q] = __float2bfloat16(v[q] - __bfloat162float(hh));
        }
        *(uint4*)((char*)Tlo + base) = *(uint4*)o;
    }
}

// ---------------------------------------------------------------------------
// HMMA split-bf16 GEMM, 128x128 CTA tile, 64x32 warp tile (2M x 4N warps),
// BK=32 chunks, 3-stage TMA pipeline, 32KB stages -> 2 CTAs/SM.
// stage (32KB): Ah 8KB, Al 8KB, Bh 8KB, Bl 8KB
// mode 0: fp32 row-major -> C0.
// mode 1 (fused QKV, gridDim.x covers N=12288): tsel = global_n>>12 selects
//   C0/C1/C2; fp32 scatter to [B,H,S,HD].
// ---------------------------------------------------------------------------
__global__ void __launch_bounds__(256, 2) gemm_hmma(
    const __nv_bfloat16* __restrict__ Ahi, const __nv_bfloat16* __restrict__ Alo,
    const __nv_bfloat16* __restrict__ Bhi, const __nv_bfloat16* __restrict__ Blo,
    float* __restrict__ C0, float* __restrict__ C1, float* __restrict__ C2,
    int mode)
{
    extern __shared__ char gsm[];
    uint32_t sb = (smem_to_u32(gsm) + 1023u) & ~1023u;
    const uint32_t stage0 = sb + 1024u;                   // 3 stages x 32KB
    const int tid = threadIdx.x, wid = tid >> 5, lane = tid & 31;
    const int bm = blockIdx.y * 128;
    const int bn_g = blockIdx.x * 128;
    const int wm = wid >> 2, wn = wid & 3;                // 2(M) x 4(N)

    if (tid == 0) {
#pragma unroll
        for (int s = 0; s < 3; s++) {
            MBARRIER_INIT(sb + s * 8, 1);          // full
            MBARRIER_INIT(sb + 24 + s * 8, 256);   // empty
        }
        FENCE_PROXY_ASYNC();
    }
    __syncthreads();

    const char* pAh = (const char*)Ahi + ((size_t)blockIdx.y << 20);
    const char* pAl = (const char*)Alo + ((size_t)blockIdx.y << 20);
    const char* pBh = (const char*)Bhi + ((size_t)blockIdx.x << 20);
    const char* pBl = (const char*)Blo + ((size_t)blockIdx.x << 20);

    auto issue = [&](int j) {
        const int s = j % 3;
        const uint32_t st = stage0 + (uint32_t)s * 32768u;
        const uint32_t mb = sb + (uint32_t)s * 8u;
        const size_t off = (size_t)j << 13;
        MBARRIER_EXPECT_TX(mb, 32768u);
        tma_bulk(st,           pAh + off, 8192u, mb);
        tma_bulk(st + 8192u,   pAl + off, 8192u, mb);
        tma_bulk(st + 16384u,  pBh + off, 8192u, mb);
        tma_bulk(st + 24576u,  pBl + off, 8192u, mb);
    };
    if (tid == 0) { issue(0); issue(1); issue(2); }

    float acc[16][4];
#pragma unroll
    for (int i = 0; i < 16; i++)
#pragma unroll
        for (int j = 0; j < 4; j++) acc[i][j] = 0.f;

    const int ra = lane & 15, c4 = lane >> 4;                      // A rows, chunk half
    const int rb = (lane & 7) + 8 * ((lane >> 3) & 1);             // B rows

    int fph[3] = {0, 0, 0};
    int eph[3] = {0, 0, 0};
    for (int i = 0; i < NKT2; i++) {
        const int s = i % 3;
        const uint32_t st = stage0 + (uint32_t)s * 32768u;
        MBARRIER_WAIT_PARITY(sb + s * 8, fph[s]); fph[s] ^= 1;

#pragma unroll
        for (int ks = 0; ks < 2; ks++) {
            uint32_t bh[2][4], bl[2][4];
#pragma unroll
            for (int ip = 0; ip < 2; ip++) {
                uint32_t off = swz64(wn * 32 + ip * 16 + rb, ks * 2 + c4);
                LDSM4(bh[ip], st + 16384u + off);
                LDSM4(bl[ip], st + 24576u + off);
            }
#pragma unroll
            for (int im = 0; im < 4; im++) {
                uint32_t off = swz64(wm * 64 + im * 16 + ra, ks * 2 + c4);
                uint32_t ah[4], al[4];
                LDSM4(ah, st + off);
                LDSM4(al, st + 8192u + off);
#pragma unroll
                for (int in = 0; in < 4; in++) {
                    const int ip = in >> 1, sel = in & 1;
                    float* c = acc[im * 4 + in];
                    mma16816(c, ah, bh[ip][sel], bh[ip][sel + 2]);
                    mma16816(c, ah, bl[ip][sel], bl[ip][sel + 2]);
                    mma16816(c, al, bh[ip][sel], bh[ip][sel + 2]);
                }
            }
        }
        MBARRIER_ARRIVE(sb + 24 + s * 8);
        if (tid == 0 && i + 3 < NKT2) {
            MBARRIER_WAIT_PARITY(sb + 24 + s * 8, eph[s]); eph[s] ^= 1;
            issue(i + 3);
        }
    }

    // ---- epilogue ----
    const int tsel = bn_g >> 12;
    const int bn = bn_g & 4095;
    float* Cout = (tsel == 0) ? C0 : ((tsel == 1) ? C1 : C2);
#pragma unroll
    for (int im = 0; im < 4; im++) {
#pragma unroll
        for (int in = 0; in < 4; in++) {
            const float* c = acc[im * 4 + in];
            int m0 = bm + wm * 64 + im * 16 + (lane >> 2);
            int n  = bn + wn * 32 + in * 8 + (lane & 3) * 2;
#pragma unroll
            for (int half = 0; half < 2; half++) {
                int m = m0 + half * 8;
                float2 v = make_float2(c[half * 2], c[half * 2 + 1]);
                if (mode == 0) {
                    *(float2*)(C0 + (size_t)m * DM + n) = v;
                } else {
                    int b = m >> 11, sq = m & 2047, h = n >> 8, hd = n & 255;
                    *(float2*)(Cout + ((size_t)(b * NH + h) * SEQ + sq) * HDIM + hd) = v;
                }
            }
        }
    }
}

// ---------------------------------------------------------------------------
// RoPE (GPT-J interleaved), fp32 in place
// ---------------------------------------------------------------------------
__global__ void __launch_bounds__(256) rope_kernel(float* __restrict__ Q, float* __restrict__ K,
                                                   const int* __restrict__ pos)
{
    int idx = blockIdx.x * blockDim.x + threadIdx.x;
    if (idx >= SEQ * 32) return;
    int i = idx & 31, s = idx >> 5;
    double inv = pow(10000.0, -(double)(2 * i) / (double)ROTD);
#pragma unroll
    for (int b = 0; b < MB; b++) {
        int p = pos[b * SEQ + s];
        double sn_, cs_;
        sincos((double)p * inv, &sn_, &cs_);
        float sn = (float)sn_, cs = (float)cs_;
#pragma unroll
        for (int h = 0; h < NH; h++) {
            size_t base = ((size_t)(b * NH + h) * SEQ + s) * HDIM + 2 * i;
            float2 q = *(float2*)(Q + base);
            *(float2*)(Q + base) = make_float2(q.x * cs - q.y * sn, q.y * cs + q.x * sn);
            float2 k = *(float2*)(K + base);
            *(float2*)(K + base) = make_float2(k.x * cs - k.y * sn, k.y * cs + k.x * sn);
        }
    }
}

// ---------------------------------------------------------------------------
// pack Q and K (fp32 [B,H,S,HD]) -> bf16 hi/lo blocked images (SW128 4KB blocks)
// ---------------------------------------------------------------------------
__global__ void __launch_bounds__(256) pack_qk(const float* __restrict__ Q, const float* __restrict__ K,
                                               __nv_bfloat16* __restrict__ Qh, __nv_bfloat16* __restrict__ Ql,
                                               __nv_bfloat16* __restrict__ Kh, __nv_bfloat16* __restrict__ Kl)
{
    size_t idx = (size_t)blockIdx.x * 256 + threadIdx.x;
    int c0 = (int)(idx & 31) << 3;
    int s  = (int)(idx >> 5) & 2047;
    int bh = (int)(idx >> 16);

    int st = s >> 5, r = s & 31, ct = c0 >> 6, cc = c0 & 63;
    size_t dst = (((size_t)(bh * 64 + st) * 4 + ct) << 12)
               + SMEM_SWIZZLE_128B((uint32_t)(r * 128 + cc * 2));
    size_t src = ((size_t)bh * SEQ + s) * HDIM + c0;

    {
        const float4* p = (const float4*)(Q + src);
        float4 v0 = p[0], v1 = p[1];
        float vv[8] = {v0.x, v0.y, v0.z, v0.w, v1.x, v1.y, v1.z, v1.w};
        __nv_bfloat16 h[8], l[8];
#pragma unroll
        for (int q = 0; q < 8; q++) split1(vv[q], h[q], l[q]);
        *(uint4*)((char*)Qh + dst) = *(uint4*)h;
        *(uint4*)((char*)Ql + dst) = *(uint4*)l;
    }
    {
        const float4* p = (const float4*)(K + src);
        float4 v0 = p[0], v1 = p[1];
        float vv[8] = {v0.x, v0.y, v0.z, v0.w, v1.x, v1.y, v1.z, v1.w};
        __nv_bfloat16 h[8], l[8];
#pragma unroll
        for (int q = 0; q < 8; q++) split1(vv[q], h[q], l[q]);
        *(uint4*)((char*)Kh + dst) = *(uint4*)h;
        *(uint4*)((char*)Kl + dst) = *(uint4*)l;
    }
}

// ---------------------------------------------------------------------------
// pack V transposed: fp32 [B,H,S,HD] -> Vt bf16 hi/lo (8KB blocks, swz64)
// ---------------------------------------------------------------------------
__global__ void __launch_bounds__(256) pack_v(const float* __restrict__ V,
                                              __nv_bfloat16* __restrict__ Vh, __nv_bfloat16* __restrict__ Vl)
{
    __shared__ float sm[32][257];
    int jt = blockIdx.x, bh = blockIdx.y;
    int t = threadIdx.x;
    int r = t >> 3, d0 = (t & 7) * 32;
    const float* src = V + ((size_t)bh * SEQ + jt * 32 + r) * HDIM + d0;
#pragma unroll
    for (int i = 0; i < 8; i++) {
        float4 v = *(const float4*)(src + i * 4);
        sm[r][d0 + i * 4 + 0] = v.x; sm[r][d0 + i * 4 + 1] = v.y;
        sm[r][d0 + i * 4 + 2] = v.z; sm[r][d0 + i * 4 + 3] = v.w;
    }
    __syncthreads();

    int d = t;
    int dt = d >> 7, rd = d & 127;
    size_t base = ((size_t)(bh * 64 + jt) * 2 + dt) << 13;
#pragma unroll
    for (int c = 0; c < 4; c++) {
        __nv_bfloat16 h[8], l[8];
#pragma unroll
        for (int jj = 0; jj < 8; jj++) split1(sm[c * 8 + jj][d], h[jj], l[jj]);
        size_t off = base + swz64(rd, c);
        *(uint4*)((char*)Vh + off) = *(uint4*)h;
        *(uint4*)((char*)Vl + off) = *(uint4*)l;
    }
}

// ---------------------------------------------------------------------------
// HMMA causal flash attention, split-bf16, online softmax (round-4 version).
// Writes fp32 CTX [B,S,D].
// ---------------------------------------------------------------------------
__global__ void __launch_bounds__(128, 1) attn_mma(
    const __nv_bfloat16* __restrict__ Qph, const __nv_bfloat16* __restrict__ Qpl,
    const __nv_bfloat16* __restrict__ Kph, const __nv_bfloat16* __restrict__ Kpl,
    const __nv_bfloat16* __restrict__ Vph, const __nv_bfloat16* __restrict__ Vpl,
    float* __restrict__ CTX)
{
    extern __shared__ char gsm[];
    uint32_t sb = (smem_to_u32(gsm) + 1023u) & ~1023u;
    const uint32_t sq = sb + 1024u;
    const uint32_t sv = sq + 65536u;

    const int qt = (int)gridDim.x - 1 - (int)blockIdx.x;
    const int bh = blockIdx.y;
    const int b  = bh >> 4, h = bh & 15;
    const int tid = threadIdx.x, w = tid >> 5, lane = tid & 31;
    const int nkt = 2 * qt + 2;

    if (tid == 0) {
        MBARRIER_INIT(sb, 1);
        MBARRIER_INIT(sb + 8, 1);
        MBARRIER_INIT(sb + 16, 1);
        MBARRIER_INIT(sb + 24, 128);
        MBARRIER_INIT(sb + 32, 128);
        FENCE_PROXY_ASYNC();
    }
    __syncthreads();

    auto issueKV = [&](int kt, int s) {
        const uint32_t st = sv + (uint32_t)s * 65536u;
        const uint32_t mb = sb + 8 + (uint32_t)s * 8u;
        MBARRIER_EXPECT_TX(mb, 65536u);
        size_t kbase = ((size_t)(bh * 64 + kt) * 4) << 12;
#pragma unroll
        for (int ct = 0; ct < 4; ct++) {
            tma_bulk(st + ct * 4096,          (const char*)Kph + kbase + ct * 4096, 4096u, mb);
            tma_bulk(st + 16384 + ct * 4096,  (const char*)Kpl + kbase + ct * 4096, 4096u, mb);
        }
        size_t vbase = ((size_t)(bh * 64 + kt) * 2) << 13;
#pragma unroll
        for (int dt = 0; dt < 2; dt++) {
            tma_bulk(st + 32768 + dt * 8192,  (const char*)Vph + vbase + dt * 8192, 8192u, mb);
            tma_bulk(st + 49152 + dt * 8192,  (const char*)Vpl + vbase + dt * 8192, 8192u, mb);
        }
    };

    if (tid == 0) {
        MBARRIER_EXPECT_TX(sb, 65536u);
#pragma unroll
        for (int sb2 = 0; sb2 < 2; sb2++) {
            size_t qbase = ((size_t)(bh * 64 + qt * 2 + sb2) * 4) << 12;
#pragma unroll
            for (int ct = 0; ct < 4; ct++) {
                tma_bulk(sq + (sb2 * 4 + ct) * 4096,          (const char*)Qph + qbase + ct * 4096, 4096u, sb);
                tma_bulk(sq + 32768 + (sb2 * 4 + ct) * 4096,  (const char*)Qpl + qbase + ct * 4096, 4096u, sb);
            }
        }
        issueKV(0, 0);
        issueKV(1, 1);
    }

    float out[32][4];
#pragma unroll
    for (int i = 0; i < 32; i++)
#pragma unroll
        for (int j = 0; j < 4; j++) out[i][j] = 0.f;
    float m0 = -1e30f, m1 = -1e30f, l0 = 0.f, l1 = 0.f;

    const int ra = lane & 15;
    const int rb = (lane & 7) + 8 * ((lane >> 3) & 1);
    const int qrow = (w & 1) * 16 + ra;
    const int row0g = qt * 64 + w * 16 + (lane >> 2);
    const int row1g = row0g + 8;
    const float SC = 0.0901699438f;

    MBARRIER_WAIT_PARITY(sb, 0);

    int fph0 = 0, fph1 = 0, eph0 = 0, eph1 = 0;
    for (int kt = 0; kt < nkt; kt++) {
        const int s = kt & 1;
        const uint32_t st = sv + (uint32_t)s * 65536u;
        if (s == 0) { MBARRIER_WAIT_PARITY(sb + 8, fph0);  fph0 ^= 1; }
        else        { MBARRIER_WAIT_PARITY(sb + 16, fph1); fph1 ^= 1; }

        float sc[4][4];
#pragma unroll
        for (int f = 0; f < 4; f++)
#pragma unroll
            for (int j = 0; j < 4; j++) sc[f][j] = 0.f;

#pragma unroll
        for (int kk = 0; kk < 16; kk++) {
            uint32_t ah[4], al[4], kh[2][4], kl[2][4];
            uint32_t aoff = (uint32_t)(((w >> 1) * 4 + (kk >> 2)) * 4096)
                          + SMEM_SWIZZLE_128B((uint32_t)(qrow * 128 + (kk & 3) * 32 + (lane >> 4) * 16));
            LDSM4(ah, sq + aoff);
            LDSM4(al, sq + 32768u + aoff);
#pragma unroll
            for (int ip = 0; ip < 2; ip++) {
                uint32_t koff = (uint32_t)((kk >> 2) * 4096)
                              + SMEM_SWIZZLE_128B((uint32_t)((ip * 16 + rb) * 128 + (kk & 3) * 32 + (lane >> 4) * 16));
                LDSM4(kh[ip], st + koff);
                LDSM4(kl[ip], st + 16384u + koff);
            }
#pragma unroll
            for (int f = 0; f < 4; f++) {
                const int ip = f >> 1, sel = f & 1;
                mma16816(sc[f], ah, kh[ip][sel], kh[ip][sel + 2]);
                mma16816(sc[f], ah, kl[ip][sel], kl[ip][sel + 2]);
                mma16816(sc[f], al, kh[ip][sel], kh[ip][sel + 2]);
            }
        }

        const bool domask = (kt * 32 + 31) > (qt * 64 + w * 16);
        float tm0 = -1e30f, tm1 = -1e30f;
#pragma unroll
        for (int f = 0; f < 4; f++) {
#pragma unroll
            for (int j = 0; j < 4; j++) {
                float v = sc[f][j] * SC;
                if (domask) {
                    int col = kt * 32 + f * 8 + (lane & 3) * 2 + (j & 1);
                    int row = (j < 2) ? row0g : row1g;
                    if (col > row) v = -1e30f;
                }
                sc[f][j] = v;
                if (j < 2) tm0 = fmaxf(tm0, v); else tm1 = fmaxf(tm1, v);
            }
        }
        tm0 = fmaxf(tm0, __shfl_xor_sync(0xffffffffu, tm0, 1));
        tm0 = fmaxf(tm0, __shfl_xor_sync(0xffffffffu, tm0, 2));
        tm1 = fmaxf(tm1, __shfl_xor_sync(0xffffffffu, tm1, 1));
        tm1 = fmaxf(tm1, __shfl_xor_sync(0xffffffffu, tm1, 2));
        float nm0 = fmaxf(m0, tm0), nm1 = fmaxf(m1, tm1);
        float a0 = ex2(m0 - nm0), a1 = ex2(m1 - nm1);
        float ls0 = 0.f, ls1 = 0.f;
#pragma unroll
        for (int f = 0; f < 4; f++) {
            sc[f][0] = ex2(sc[f][0] - nm0); ls0 += sc[f][0];
            sc[f][1] = ex2(sc[f][1] - nm0); ls0 += sc[f][1];
            sc[f][2] = ex2(sc[f][2] - nm1); ls1 += sc[f][2];
            sc[f][3] = ex2(sc[f][3] - nm1); ls1 += sc[f][3];
        }
        ls0 += __shfl_xor_sync(0xffffffffu, ls0, 1);
        ls0 += __shfl_xor_sync(0xffffffffu, ls0, 2);
        ls1 += __shfl_xor_sync(0xffffffffu, ls1, 1);
        ls1 += __shfl_xor_sync(0xffffffffu, ls1, 2);
        l0 = l0 * a0 + ls0; l1 = l1 * a1 + ls1;
        m0 = nm0; m1 = nm1;

#pragma unroll
        for (int i = 0; i < 32; i++) {
            out[i][0] *= a0; out[i][1] *= a0;
            out[i][2] *= a1; out[i][3] *= a1;
        }

        uint32_t pah[2][4], pal[2][4];
#pragma unroll
        for (int kc = 0; kc < 2; kc++) {
            float* f0 = sc[2 * kc];
            float* f1 = sc[2 * kc + 1];
            pksplit2(f0[0], f0[1], pah[kc][0], pal[kc][0]);
            pksplit2(f0[2], f0[3], pah[kc][1], pal[kc][1]);
            pksplit2(f1[0], f1[1], pah[kc][2], pal[kc][2]);
            pksplit2(f1[2], f1[3], pah[kc][3], pal[kc][3]);
        }

#pragma unroll
        for (int kc = 0; kc < 2; kc++) {
#pragma unroll
            for (int dp = 0; dp < 16; dp++) {
                uint32_t vh[4], vl[4];
                int rr = (dp & 7) * 16 + rb;
                uint32_t voff = (uint32_t)((dp >> 3) * 8192) + swz64(rr, kc * 2 + (lane >> 4));
                LDSM4(vh, st + 32768u + voff);
                LDSM4(vl, st + 49152u + voff);
#pragma unroll
                for (int sel = 0; sel < 2; sel++) {
                    float* c = out[2 * dp + sel];
                    mma16816(c, pah[kc], vh[sel], vh[sel + 2]);
                    mma16816(c, pah[kc], vl[sel], vl[sel + 2]);
                    mma16816(c, pal[kc], vh[sel], vh[sel + 2]);
                }
            }
        }

        MBARRIER_ARRIVE(sb + 24 + s * 8);
        if (tid == 0 && kt + 2 < nkt) {
            if (s == 0) { MBARRIER_WAIT_PARITY(sb + 24, eph0); eph0 ^= 1; }
            else        { MBARRIER_WAIT_PARITY(sb + 32, eph1); eph1 ^= 1; }
            issueKV(kt + 2, s);
        }
    }

    float inv0 = 1.0f / l0, inv1 = 1.0f / l1;
    float* base0 = CTX + ((size_t)(b * SEQ + row0g)) * DM + h * HDIM;
    float* base1 = CTX + ((size_t)(b * SEQ + row1g)) * DM + h * HDIM;
#pragma unroll
    for (int nf = 0; nf < 32; nf++) {
        int d = nf * 8 + (lane & 3) * 2;
        *(float2*)(base0 + d) = make_float2(out[nf][0] * inv0, out[nf][1] * inv0);
        *(float2*)(base1 + d) = make_float2(out[nf][2] * inv1, out[nf][3] * inv1);
    }
}

// ---------------------------------------------------------------------------
extern "C" void kernel_launch(void* const* d_in, const int* in_sizes, int n_in,
                              void* d_out, int out_size)
{
    const float* X   = (const float*)d_in[0];
    const int*   pos = (const int*)  d_in[1];
    const float* W[4] = { (const float*)d_in[2], (const float*)d_in[3],
                          (const float*)d_in[4], (const float*)d_in[5] };
    float* out = (float*)d_out;

    float *Qg, *Kg, *Vg, *CTX;
    __nv_bfloat16 *Xhi, *Xlo, *Chi, *Clo, *WThi, *WTlo;
    __nv_bfloat16 *Qph, *Qpl, *Kph, *Kpl, *Vph, *Vpl;
    cudaGetSymbolAddress((void**)&Qg,  g_Q);
    cudaGetSymbolAddress((void**)&Kg,  g_K);
    cudaGetSymbolAddress((void**)&Vg,  g_V);
    cudaGetSymbolAddress((void**)&CTX, g_CTX);
    cudaGetSymbolAddress((void**)&Xhi, g_Xhi);
    cudaGetSymbolAddress((void**)&Xlo, g_Xlo);
    cudaGetSymbolAddress((void**)&Chi, g_Chi);
    cudaGetSymbolAddress((void**)&Clo, g_Clo);
    cudaGetSymbolAddress((void**)&WThi, g_WThi);
    cudaGetSymbolAddress((void**)&WTlo, g_WTlo);
    cudaGetSymbolAddress((void**)&Qph, g_Qph);
    cudaGetSymbolAddress((void**)&Qpl, g_Qpl);
    cudaGetSymbolAddress((void**)&Kph, g_Kph);
    cudaGetSymbolAddress((void**)&Kpl, g_Kpl);
    cudaGetSymbolAddress((void**)&Vph, g_Vph);
    cudaGetSymbolAddress((void**)&Vpl, g_Vpl);

    const int GEMM_SMEM = 1024 + 1024 + 3 * 32768;          // 100352 -> 2 CTAs/SM
    const int ATTN_SMEM = 1024 + 1024 + 65536 + 2 * 65536;  // 198656
    cudaFuncSetAttribute(gemm_hmma, cudaFuncAttributeMaxDynamicSharedMemorySize, GEMM_SMEM);
    cudaFuncSetAttribute(attn_mma, cudaFuncAttributeMaxDynamicSharedMemorySize, ATTN_SMEM);

    const size_t WSZ = (size_t)DM * DM;
    dim3 trg(DM / 32, DM / 32);

    // pack GEMM operands (128x32 blocks, swz64)
    split_rm_tiled<<<8192, 256>>>(X, Xhi, Xlo);
    for (int w = 0; w < 4; w++)
        split_tr_tiled<<<trg, 256>>>(W[w], WThi + (size_t)w * WSZ, WTlo + (size_t)w * WSZ);

    // fused QKV projection (fp32 scatter to [B,H,S,HD])
    gemm_hmma<<<dim3(96, 32), 256, GEMM_SMEM>>>(Xhi, Xlo, WThi, WTlo, Qg, Kg, Vg, 1);

    rope_kernel<<<(SEQ * 32 + 255) / 256, 256>>>(Qg, Kg, pos);

    // pack attention operands
    pack_qk<<<8192, 256>>>(Qg, Kg, Qph, Qpl, Kph, Kpl);
    pack_v<<<dim3(64, 32), 256>>>(Vg, Vph, Vpl);

    // attention (writes fp32 CTX)
    attn_mma<<<dim3(32, 32), 128, ATTN_SMEM>>>(Qph, Qpl, Kph, Kpl, Vph, Vpl, CTX);

    // output projection
    split_rm_tiled<<<8192, 256>>>(CTX, Chi, Clo);
    gemm_hmma<<<dim3(32, 32), 256, GEMM_SMEM>>>(Chi, Clo, WThi + 3 * WSZ, WTlo + 3 * WSZ,
                                                out, nullptr, nullptr, 0);
}

// round 9
// speedup vs baseline: 1.1954x; 1.0275x over previous
#include <cuda_runtime.h>
#include <cuda_bf16.h>
#include <stdint.h>
#include <math.h>

#define MB   2
#define SEQ  2048
#define DM   4096
#define NH   16
#define HDIM 256
#define ROTD 64

#define BK 32
#define NKT2 128            // K-chunks of 32
#define BLK2 8192           // one 128x32 bf16 block, 64B-row swizzled

// ---------------- scratch ----------------
__device__ float g_Q[(size_t)MB * NH * SEQ * HDIM];
__device__ float g_K[(size_t)MB * NH * SEQ * HDIM];
__device__ float g_V[(size_t)MB * NH * SEQ * HDIM];
__device__ float g_CTX[(size_t)MB * SEQ * DM];
__device__ float2 g_rope[(size_t)MB * SEQ * 32];

// tiled + swizzled bf16 operand images (128x32 blocks, 8KB each)
__device__ __align__(1024) __nv_bfloat16 g_Xhi[(size_t)DM * DM];
__device__ __align__(1024) __nv_bfloat16 g_Xlo[(size_t)DM * DM];
__device__ __align__(1024) __nv_bfloat16 g_Chi[(size_t)DM * DM];
__device__ __align__(1024) __nv_bfloat16 g_Clo[(size_t)DM * DM];
__device__ __align__(1024) __nv_bfloat16 g_WThi[4][(size_t)DM * DM];
__device__ __align__(1024) __nv_bfloat16 g_WTlo[4][(size_t)DM * DM];

// attention packed operands
__device__ __align__(1024) __nv_bfloat16 g_Qph[(size_t)32 * 2048 * 256];
__device__ __align__(1024) __nv_bfloat16 g_Qpl[(size_t)32 * 2048 * 256];
__device__ __align__(1024) __nv_bfloat16 g_Kph[(size_t)32 * 2048 * 256];
__device__ __align__(1024) __nv_bfloat16 g_Kpl[(size_t)32 * 2048 * 256];
__device__ __align__(1024) __nv_bfloat16 g_Vph[(size_t)32 * 2048 * 256];
__device__ __align__(1024) __nv_bfloat16 g_Vpl[(size_t)32 * 2048 * 256];

// ---------------- helpers ----------------
__device__ __forceinline__ uint32_t smem_to_u32(const void* p) {
    uint32_t a;
    asm("{ .reg .u64 t; cvta.to.shared.u64 t, %1; cvt.u32.u64 %0, t; }" : "=r"(a) : "l"(p));
    return a;
}
#define MBARRIER_INIT(a, c) \
    asm volatile("mbarrier.init.shared.b64 [%0], %1;" :: "r"((uint32_t)(a)), "r"((uint32_t)(c)) : "memory")
#define MBARRIER_EXPECT_TX(a, tx) \
    asm volatile("mbarrier.arrive.expect_tx.shared.b64 _, [%0], %1;" :: "r"((uint32_t)(a)), "r"((uint32_t)(tx)) : "memory")
#define MBARRIER_ARRIVE(a) \
    asm volatile("mbarrier.arrive.shared.b64 _, [%0];" :: "r"((uint32_t)(a)) : "memory")
#define FENCE_PROXY_ASYNC() asm volatile("fence.proxy.async.shared::cta;" ::: "memory")
#define MBARRIER_WAIT_PARITY(mbar_smem_addr, phase_parity) do { \
    uint32_t _mbar = (uint32_t)(mbar_smem_addr); \
    uint32_t _parity = (uint32_t)(phase_parity); \
    uint32_t _done; \
    asm volatile("{\n\t.reg .pred p;\n\t" \
        "mbarrier.try_wait.parity.acquire.cta.shared::cta.b64 p, [%1], %2;\n\t" \
        "selp.b32 %0, 1, 0, p;\n\t}" \
        : "=r"(_done) : "r"(_mbar), "r"(_parity) : "memory"); \
    if (!_done) { \
        asm volatile("{\n\t.reg .pred P1;\n\t" \
            "WAIT_LOOP_%=:\n\t" \
            "mbarrier.try_wait.parity.acquire.cta.shared::cta.b64 P1, [%0], %1, 0x989680;\n\t" \
            "@P1 bra.uni WAIT_DONE_%=;\n\t" \
            "bra.uni WAIT_LOOP_%=;\n\t" \
            "WAIT_DONE_%=:\n\t}" \
            :: "r"(_mbar), "r"(_parity) : "memory"); \
    } \
} while(0)

__device__ __forceinline__ void tma_bulk(uint32_t dst, const void* src, uint32_t bytes, uint32_t mbar) {
    asm volatile("cp.async.bulk.shared::cluster.global.mbarrier::complete_tx::bytes [%0], [%1], %2, [%3];"
        :: "r"(dst), "l"(src), "r"(bytes), "r"(mbar) : "memory");
}

#define SMEM_SWIZZLE_128B(x) ((x) ^ (((x) >> 3) & 0x70))
__device__ __forceinline__ uint32_t swz64(int r, int c) {
    return (uint32_t)(r * 64 + ((c ^ ((r >> 1) & 3)) << 4));
}

#define LDSM4(r, addr) \
    asm volatile("ldmatrix.sync.aligned.m8n8.x4.shared.b16 {%0,%1,%2,%3}, [%4];" \
        : "=r"((r)[0]), "=r"((r)[1]), "=r"((r)[2]), "=r"((r)[3]) : "r"(addr))

__device__ __forceinline__ void mma16816(float* c, const uint32_t* a, uint32_t b0, uint32_t b1) {
    asm volatile("mma.sync.aligned.m16n8k16.row.col.f32.bf16.bf16.f32 "
        "{%0,%1,%2,%3}, {%4,%5,%6,%7}, {%8,%9}, {%0,%1,%2,%3};"
        : "+f"(c[0]), "+f"(c[1]), "+f"(c[2]), "+f"(c[3])
        : "r"(a[0]), "r"(a[1]), "r"(a[2]), "r"(a[3]), "r"(b0), "r"(b1));
}

__device__ __forceinline__ float ex2(float x) {
    float r;
    asm("ex2.approx.f32 %0, %1;" : "=f"(r) : "f"(x));
    return r;
}

__device__ __forceinline__ void split1(float v, __nv_bfloat16& h, __nv_bfloat16& l) {
    h = __float2bfloat16(v);
    l = __float2bfloat16(v - __bfloat162float(h));
}
__device__ __forceinline__ uint32_t pk2(float a, float b) {
    __nv_bfloat162 t = __floats2bfloat162_rn(a, b);
    return *(uint32_t*)&t;
}
__device__ __forceinline__ void pksplit2(float a, float b, uint32_t& hi, uint32_t& lo) {
    __nv_bfloat16 ah = __float2bfloat16(a), bh = __float2bfloat16(b);
    __nv_bfloat162 hp; hp.x = ah; hp.y = bh;
    hi = *(uint32_t*)&hp;
    lo = pk2(a - __bfloat162float(ah), b - __bfloat162float(bh));
}

// ---------------------------------------------------------------------------
// rope table: g_rope[b][s][i] = (cos, sin)
// ---------------------------------------------------------------------------
__global__ void __launch_bounds__(256) rope_tab(const int* __restrict__ pos, float2* __restrict__ tab)
{
    int idx = blockIdx.x * 256 + threadIdx.x;
    if (idx >= MB * SEQ * 32) return;
    int i = idx & 31, s = (idx >> 5) & (SEQ - 1), b = idx >> 16;
    int p = pos[b * SEQ + s];
    double inv = pow(10000.0, -(double)(2 * i) / (double)ROTD);
    double sn, cs;
    sincos((double)p * inv, &sn, &cs);
    tab[idx] = make_float2((float)cs, (float)sn);
}

// ---------------------------------------------------------------------------
// split fp32 row-major [4096][4096] -> 128x32 blocks, 64B-row swizzle
// ---------------------------------------------------------------------------
__global__ void __launch_bounds__(256) split_rm_tiled(const float* __restrict__ in,
                                                      __nv_bfloat16* __restrict__ hi,
                                                      __nv_bfloat16* __restrict__ lo)
{
    size_t idx = (size_t)blockIdx.x * 256 + threadIdx.x;
    int m  = (int)(idx >> 9);
    int k  = (int)(idx & 511) << 3;
    const float4* p = (const float4*)(in + ((size_t)m << 12) + k);
    float4 v0 = p[0], v1 = p[1];

    __nv_bfloat16 h[8], l[8];
    split1(v0.x, h[0], l[0]); split1(v0.y, h[1], l[1]);
    split1(v0.z, h[2], l[2]); split1(v0.w, h[3], l[3]);
    split1(v1.x, h[4], l[4]); split1(v1.y, h[5], l[5]);
    split1(v1.z, h[6], l[6]); split1(v1.w, h[7], l[7]);

    int mt = m >> 7, r = m & 127, kt = k >> 5, c = (k >> 3) & 3;
    size_t base = ((size_t)(mt * NKT2 + kt)) * BLK2 + swz64(r, c);
    *(uint4*)((char*)hi + base) = *(uint4*)h;
    *(uint4*)((char*)lo + base) = *(uint4*)l;
}

// ---------------------------------------------------------------------------
// W [K][N] fp32 -> BT 128x32 blocks, 64B-row swizzle (transpose + split)
// ---------------------------------------------------------------------------
__global__ void __launch_bounds__(256) split_tr_tiled(const float* __restrict__ W,
                                                      __nv_bfloat16* __restrict__ Thi,
                                                      __nv_bfloat16* __restrict__ Tlo)
{
    __shared__ float t[32][33];
    int w = threadIdx.x;
    int nb = blockIdx.x * 32, kb = blockIdx.y * 32;
    int tx = w & 31, ty = w >> 5;
#pragma unroll
    for (int j = 0; j < 4; j++)
        t[ty + j * 8][tx] = W[(size_t)(kb + ty + j * 8) * DM + nb + tx];
    __syncthreads();

    int half = w >> 7, w7 = w & 127;
    int nn = w7 >> 2, kc = (w7 & 3) * 8;
    int n = nb + nn, kk = kb + kc;
    float v[8];
#pragma unroll
    for (int q = 0; q < 8; q++) v[q] = t[kc + q][nn];

    int nt = n >> 7, r = n & 127, kt = kk >> 5, c = (kk >> 3) & 3;
    size_t base = ((size_t)(nt * NKT2 + kt)) * BLK2 + swz64(r, c);
    __nv_bfloat16 o[8];
    if (half == 0) {
#pragma unroll
        for (int q = 0; q < 8; q++) o[q] = __float2bfloat16(v[q]);
        *(uint4*)((char*)Thi + base) = *(uint4*)o;
    } else {
#pragma unroll
        for (int q = 0; q < 8; q++) {
            __nv_bfloat16 hh = __float2bfloat16(v[q]);
            o[q] = __float2bfloat16(v[q] - __bfloat162float(hh));
        }
        *(uint4*)((char*)Tlo + base) = *(uint4*)o;
    }
}

// ---------------------------------------------------------------------------
// HMMA split-bf16 GEMM (round-8 best): 128x128 CTA, BK=32, 3 stages, 2 CTAs/SM
// ---------------------------------------------------------------------------
__global__ void __launch_bounds__(256, 2) gemm_hmma(
    const __nv_bfloat16* __restrict__ Ahi, const __nv_bfloat16* __restrict__ Alo,
    const __nv_bfloat16* __restrict__ Bhi, const __nv_bfloat16* __restrict__ Blo,
    float* __restrict__ C0, float* __restrict__ C1, float* __restrict__ C2,
    int mode)
{
    extern __shared__ char gsm[];
    uint32_t sb = (smem_to_u32(gsm) + 1023u) & ~1023u;
    const uint32_t stage0 = sb + 1024u;                   // 3 stages x 32KB
    const int tid = threadIdx.x, wid = tid >> 5, lane = tid & 31;
    const int bm = blockIdx.y * 128;
    const int bn_g = blockIdx.x * 128;
    const int wm = wid >> 2, wn = wid & 3;                // 2(M) x 4(N)

    if (tid == 0) {
#pragma unroll
        for (int s = 0; s < 3; s++) {
            MBARRIER_INIT(sb + s * 8, 1);          // full
            MBARRIER_INIT(sb + 24 + s * 8, 256);   // empty
        }
        FENCE_PROXY_ASYNC();
    }
    __syncthreads();

    const char* pAh = (const char*)Ahi + ((size_t)blockIdx.y << 20);
    const char* pAl = (const char*)Alo + ((size_t)blockIdx.y << 20);
    const char* pBh = (const char*)Bhi + ((size_t)blockIdx.x << 20);
    const char* pBl = (const char*)Blo + ((size_t)blockIdx.x << 20);

    auto issue = [&](int j) {
        const int s = j % 3;
        const uint32_t st = stage0 + (uint32_t)s * 32768u;
        const uint32_t mb = sb + (uint32_t)s * 8u;
        const size_t off = (size_t)j << 13;
        MBARRIER_EXPECT_TX(mb, 32768u);
        tma_bulk(st,           pAh + off, 8192u, mb);
        tma_bulk(st + 8192u,   pAl + off, 8192u, mb);
        tma_bulk(st + 16384u,  pBh + off, 8192u, mb);
        tma_bulk(st + 24576u,  pBl + off, 8192u, mb);
    };
    if (tid == 0) { issue(0); issue(1); issue(2); }

    float acc[16][4];
#pragma unroll
    for (int i = 0; i < 16; i++)
#pragma unroll
        for (int j = 0; j < 4; j++) acc[i][j] = 0.f;

    const int ra = lane & 15, c4 = lane >> 4;
    const int rb = (lane & 7) + 8 * ((lane >> 3) & 1);

    int fph[3] = {0, 0, 0};
    int eph[3] = {0, 0, 0};
    for (int i = 0; i < NKT2; i++) {
        const int s = i % 3;
        const uint32_t st = stage0 + (uint32_t)s * 32768u;
        MBARRIER_WAIT_PARITY(sb + s * 8, fph[s]); fph[s] ^= 1;

#pragma unroll
        for (int ks = 0; ks < 2; ks++) {
            uint32_t bh[2][4], bl[2][4];
#pragma unroll
            for (int ip = 0; ip < 2; ip++) {
                uint32_t off = swz64(wn * 32 + ip * 16 + rb, ks * 2 + c4);
                LDSM4(bh[ip], st + 16384u + off);
                LDSM4(bl[ip], st + 24576u + off);
            }
#pragma unroll
            for (int im = 0; im < 4; im++) {
                uint32_t off = swz64(wm * 64 + im * 16 + ra, ks * 2 + c4);
                uint32_t ah[4], al[4];
                LDSM4(ah, st + off);
                LDSM4(al, st + 8192u + off);
#pragma unroll
                for (int in = 0; in < 4; in++) {
                    const int ip = in >> 1, sel = in & 1;
                    float* c = acc[im * 4 + in];
                    mma16816(c, ah, bh[ip][sel], bh[ip][sel + 2]);
                    mma16816(c, ah, bl[ip][sel], bl[ip][sel + 2]);
                    mma16816(c, al, bh[ip][sel], bh[ip][sel + 2]);
                }
            }
        }
        MBARRIER_ARRIVE(sb + 24 + s * 8);
        if (tid == 0 && i + 3 < NKT2) {
            MBARRIER_WAIT_PARITY(sb + 24 + s * 8, eph[s]); eph[s] ^= 1;
            issue(i + 3);
        }
    }

    const int tsel = bn_g >> 12;
    const int bn = bn_g & 4095;
    float* Cout = (tsel == 0) ? C0 : ((tsel == 1) ? C1 : C2);
#pragma unroll
    for (int im = 0; im < 4; im++) {
#pragma unroll
        for (int in = 0; in < 4; in++) {
            const float* c = acc[im * 4 + in];
            int m0 = bm + wm * 64 + im * 16 + (lane >> 2);
            int n  = bn + wn * 32 + in * 8 + (lane & 3) * 2;
#pragma unroll
            for (int half = 0; half < 2; half++) {
                int m = m0 + half * 8;
                float2 v = make_float2(c[half * 2], c[half * 2 + 1]);
                if (mode == 0) {
                    *(float2*)(C0 + (size_t)m * DM + n) = v;
                } else {
                    int b = m >> 11, sq = m & 2047, h = n >> 8, hd = n & 255;
                    *(float2*)(Cout + ((size_t)(b * NH + h) * SEQ + sq) * HDIM + hd) = v;
                }
            }
        }
    }
}

// ---------------------------------------------------------------------------
// pack Q and K + fused RoPE: fp32 [B,H,S,HD] -> bf16 hi/lo blocked images
// ---------------------------------------------------------------------------
__global__ void __launch_bounds__(256) pack_qk(const float* __restrict__ Q, const float* __restrict__ K,
                                               const float2* __restrict__ tab,
                                               __nv_bfloat16* __restrict__ Qh, __nv_bfloat16* __restrict__ Ql,
                                               __nv_bfloat16* __restrict__ Kh, __nv_bfloat16* __restrict__ Kl)
{
    size_t idx = (size_t)blockIdx.x * 256 + threadIdx.x;
    int c0 = (int)(idx & 31) << 3;
    int s  = (int)(idx >> 5) & 2047;
    int bh = (int)(idx >> 16);
    int b  = bh >> 4;

    int st = s >> 5, r = s & 31, ct = c0 >> 6, cc = c0 & 63;
    size_t dst = (((size_t)(bh * 64 + st) * 4 + ct) << 12)
               + SMEM_SWIZZLE_128B((uint32_t)(r * 128 + cc * 2));
    size_t src = ((size_t)bh * SEQ + s) * HDIM + c0;

    float2 rt[4];
    const bool dorope = (c0 < ROTD);
    if (dorope) {
#pragma unroll
        for (int q = 0; q < 4; q++)
            rt[q] = tab[(size_t)(b * SEQ + s) * 32 + (c0 >> 1) + q];
    }

    {
        const float4* p = (const float4*)(Q + src);
        float4 v0 = p[0], v1 = p[1];
        float vv[8] = {v0.x, v0.y, v0.z, v0.w, v1.x, v1.y, v1.z, v1.w};
        if (dorope) {
#pragma unroll
            for (int q = 0; q < 4; q++) {
                float x = vv[2 * q], y = vv[2 * q + 1];
                vv[2 * q]     = x * rt[q].x - y * rt[q].y;
                vv[2 * q + 1] = y * rt[q].x + x * rt[q].y;
            }
        }
        __nv_bfloat16 h[8], l[8];
#pragma unroll
        for (int q = 0; q < 8; q++) split1(vv[q], h[q], l[q]);
        *(uint4*)((char*)Qh + dst) = *(uint4*)h;
        *(uint4*)((char*)Ql + dst) = *(uint4*)l;
    }
    {
        const float4* p = (const float4*)(K + src);
        float4 v0 = p[0], v1 = p[1];
        float vv[8] = {v0.x, v0.y, v0.z, v0.w, v1.x, v1.y, v1.z, v1.w};
        if (dorope) {
#pragma unroll
            for (int q = 0; q < 4; q++) {
                float x = vv[2 * q], y = vv[2 * q + 1];
                vv[2 * q]     = x * rt[q].x - y * rt[q].y;
                vv[2 * q + 1] = y * rt[q].x + x * rt[q].y;
            }
        }
        __nv_bfloat16 h[8], l[8];
#pragma unroll
        for (int q = 0; q < 8; q++) split1(vv[q], h[q], l[q]);
        *(uint4*)((char*)Kh + dst) = *(uint4*)h;
        *(uint4*)((char*)Kl + dst) = *(uint4*)l;
    }
}

// ---------------------------------------------------------------------------
// pack V transposed: fp32 [B,H,S,HD] -> Vt bf16 hi/lo (8KB blocks, swz64)
// ---------------------------------------------------------------------------
__global__ void __launch_bounds__(256) pack_v(const float* __restrict__ V,
                                              __nv_bfloat16* __restrict__ Vh, __nv_bfloat16* __restrict__ Vl)
{
    __shared__ float sm[32][257];
    int jt = blockIdx.x, bh = blockIdx.y;
    int t = threadIdx.x;
    int r = t >> 3, d0 = (t & 7) * 32;
    const float* src = V + ((size_t)bh * SEQ + jt * 32 + r) * HDIM + d0;
#pragma unroll
    for (int i = 0; i < 8; i++) {
        float4 v = *(const float4*)(src + i * 4);
        sm[r][d0 + i * 4 + 0] = v.x; sm[r][d0 + i * 4 + 1] = v.y;
        sm[r][d0 + i * 4 + 2] = v.z; sm[r][d0 + i * 4 + 3] = v.w;
    }
    __syncthreads();

    int d = t;
    int dt = d >> 7, rd = d & 127;
    size_t base = ((size_t)(bh * 64 + jt) * 2 + dt) << 13;
#pragma unroll
    for (int c = 0; c < 4; c++) {
        __nv_bfloat16 h[8], l[8];
#pragma unroll
        for (int jj = 0; jj < 8; jj++) split1(sm[c * 8 + jj][d], h[jj], l[jj]);
        size_t off = base + swz64(rd, c);
        *(uint4*)((char*)Vh + off) = *(uint4*)h;
        *(uint4*)((char*)Vl + off) = *(uint4*)l;
    }
}

// ---------------------------------------------------------------------------
// HMMA causal flash attention, split-bf16, online softmax.
// 256 threads (8 warps, 2/SMSP): warp w -> row group mq=w&3 (16 rows of the
// 64-row q-tile), key half kh=w>>2 (16 of the 32-key tile). Cross-warp softmax
// via smem exchanges; epilogue partial-out reduction through KV stage smem.
// ---------------------------------------------------------------------------
__global__ void __launch_bounds__(256, 1) attn_mma(
    const __nv_bfloat16* __restrict__ Qph, const __nv_bfloat16* __restrict__ Qpl,
    const __nv_bfloat16* __restrict__ Kph, const __nv_bfloat16* __restrict__ Kpl,
    const __nv_bfloat16* __restrict__ Vph, const __nv_bfloat16* __restrict__ Vpl,
    float* __restrict__ CTX)
{
    extern __shared__ char gsm[];
    const uint32_t g0 = smem_to_u32(gsm);
    const uint32_t sb = (g0 + 1023u) & ~1023u;
    float* mbuf = (float*)(gsm + (sb - g0) + 128);   // 128 floats
    float* sbuf = mbuf + 128;                        // 128 floats
    const uint32_t sq = sb + 2048u;                  // Q: hi 32KB, lo 32KB
    const uint32_t sv = sq + 65536u;                 // 2 stages x 64KB
    float* red = (float*)(gsm + (sv - g0));          // epilogue reduce buffer

    const int qt = (int)gridDim.x - 1 - (int)blockIdx.x;
    const int bh = blockIdx.y;
    const int b  = bh >> 4, h = bh & 15;
    const int tid = threadIdx.x, w = tid >> 5, lane = tid & 31;
    const int mq = w & 3, kh = w >> 2;
    const int nkt = 2 * qt + 2;

    if (tid == 0) {
        MBARRIER_INIT(sb, 1);
        MBARRIER_INIT(sb + 8, 1);
        MBARRIER_INIT(sb + 16, 1);
        MBARRIER_INIT(sb + 24, 256);
        MBARRIER_INIT(sb + 32, 256);
        FENCE_PROXY_ASYNC();
    }
    __syncthreads();

    auto issueKV = [&](int kt, int s) {
        const uint32_t st = sv + (uint32_t)s * 65536u;
        const uint32_t mb = sb + 8 + (uint32_t)s * 8u;
        MBARRIER_EXPECT_TX(mb, 65536u);
        size_t kbase = ((size_t)(bh * 64 + kt) * 4) << 12;
#pragma unroll
        for (int ct = 0; ct < 4; ct++) {
            tma_bulk(st + ct * 4096,          (const char*)Kph + kbase + ct * 4096, 4096u, mb);
            tma_bulk(st + 16384 + ct * 4096,  (const char*)Kpl + kbase + ct * 4096, 4096u, mb);
        }
        size_t vbase = ((size_t)(bh * 64 + kt) * 2) << 13;
#pragma unroll
        for (int dt = 0; dt < 2; dt++) {
            tma_bulk(st + 32768 + dt * 8192,  (const char*)Vph + vbase + dt * 8192, 8192u, mb);
            tma_bulk(st + 49152 + dt * 8192,  (const char*)Vpl + vbase + dt * 8192, 8192u, mb);
        }
    };

    if (tid == 0) {
        MBARRIER_EXPECT_TX(sb, 65536u);
#pragma unroll
        for (int sb2 = 0; sb2 < 2; sb2++) {
            size_t qbase = ((size_t)(bh * 64 + qt * 2 + sb2) * 4) << 12;
#pragma unroll
            for (int ct = 0; ct < 4; ct++) {
                tma_bulk(sq + (sb2 * 4 + ct) * 4096,          (const char*)Qph + qbase + ct * 4096, 4096u, sb);
                tma_bulk(sq + 32768 + (sb2 * 4 + ct) * 4096,  (const char*)Qpl + qbase + ct * 4096, 4096u, sb);
            }
        }
        issueKV(0, 0);
        issueKV(1, 1);
    }

    float out[32][4];
#pragma unroll
    for (int i = 0; i < 32; i++)
#pragma unroll
        for (int j = 0; j < 4; j++) out[i][j] = 0.f;
    float m0 = -1e30f, m1 = -1e30f, l0 = 0.f, l1 = 0.f;

    const int ra = lane & 15;
    const int rb = (lane & 7) + 8 * ((lane >> 3) & 1);
    const int qrow = (mq & 1) * 16 + ra;
    const int row0g = qt * 64 + mq * 16 + (lane >> 2);
    const int row1g = row0g + 8;
    const int xrow0 = mq * 16 + (lane >> 2);     // 0..63, for exchange buffers
    const float SC = 0.0901699438f;

    MBARRIER_WAIT_PARITY(sb, 0);

    int fph0 = 0, fph1 = 0, eph0 = 0, eph1 = 0;
    for (int kt = 0; kt < nkt; kt++) {
        const int s = kt & 1;
        const uint32_t st = sv + (uint32_t)s * 65536u;
        if (s == 0) { MBARRIER_WAIT_PARITY(sb + 8, fph0);  fph0 ^= 1; }
        else        { MBARRIER_WAIT_PARITY(sb + 16, fph1); fph1 ^= 1; }

        // ---- scores for this warp's 16 keys ----
        float sc[2][4];
#pragma unroll
        for (int f = 0; f < 2; f++)
#pragma unroll
            for (int j = 0; j < 4; j++) sc[f][j] = 0.f;

#pragma unroll
        for (int kk = 0; kk < 16; kk++) {
            uint32_t ah[4], al[4], kfh[4], kfl[4];
            uint32_t aoff = (uint32_t)(((mq >> 1) * 4 + (kk >> 2)) * 4096)
                          + SMEM_SWIZZLE_128B((uint32_t)(qrow * 128 + (kk & 3) * 32 + (lane >> 4) * 16));
            LDSM4(ah, sq + aoff);
            LDSM4(al, sq + 32768u + aoff);
            uint32_t koff = (uint32_t)((kk >> 2) * 4096)
                          + SMEM_SWIZZLE_128B((uint32_t)((kh * 16 + rb) * 128 + (kk & 3) * 32 + (lane >> 4) * 16));
            LDSM4(kfh, st + koff);
            LDSM4(kfl, st + 16384u + koff);
#pragma unroll
            for (int f = 0; f < 2; f++) {
                mma16816(sc[f], ah, kfh[f], kfh[f + 2]);
                mma16816(sc[f], ah, kfl[f], kfl[f + 2]);
                mma16816(sc[f], al, kfh[f], kfh[f + 2]);
            }
        }

        // ---- local mask + max over this warp's 16 keys ----
        const bool domask = (kt * 32 + kh * 16 + 15) > (qt * 64 + mq * 16);
        float tm0 = -1e30f, tm1 = -1e30f;
#pragma unroll
        for (int f = 0; f < 2; f++) {
#pragma unroll
            for (int j = 0; j < 4; j++) {
                float v = sc[f][j] * SC;
                if (domask) {
                    int col = kt * 32 + kh * 16 + f * 8 + (lane & 3) * 2 + (j & 1);
                    int row = (j < 2) ? row0g : row1g;
                    if (col > row) v = -1e30f;
                }
                sc[f][j] = v;
                if (j < 2) tm0 = fmaxf(tm0, v); else tm1 = fmaxf(tm1, v);
            }
        }
        tm0 = fmaxf(tm0, __shfl_xor_sync(0xffffffffu, tm0, 1));
        tm0 = fmaxf(tm0, __shfl_xor_sync(0xffffffffu, tm0, 2));
        tm1 = fmaxf(tm1, __shfl_xor_sync(0xffffffffu, tm1, 1));
        tm1 = fmaxf(tm1, __shfl_xor_sync(0xffffffffu, tm1, 2));

        // ---- cross-warp max exchange ----
        if ((lane & 3) == 0) {
            mbuf[kh * 64 + xrow0]     = tm0;
            mbuf[kh * 64 + xrow0 + 8] = tm1;
        }
        __syncthreads();
        tm0 = fmaxf(tm0, mbuf[(kh ^ 1) * 64 + xrow0]);
        tm1 = fmaxf(tm1, mbuf[(kh ^ 1) * 64 + xrow0 + 8]);

        float nm0 = fmaxf(m0, tm0), nm1 = fmaxf(m1, tm1);
        float a0 = ex2(m0 - nm0), a1 = ex2(m1 - nm1);
        float ls0 = 0.f, ls1 = 0.f;
#pragma unroll
        for (int f = 0; f < 2; f++) {
            sc[f][0] = ex2(sc[f][0] - nm0); ls0 += sc[f][0];
            sc[f][1] = ex2(sc[f][1] - nm0); ls0 += sc[f][1];
            sc[f][2] = ex2(sc[f][2] - nm1); ls1 += sc[f][2];
            sc[f][3] = ex2(sc[f][3] - nm1); ls1 += sc[f][3];
        }
        ls0 += __shfl_xor_sync(0xffffffffu, ls0, 1);
        ls0 += __shfl_xor_sync(0xffffffffu, ls0, 2);
        ls1 += __shfl_xor_sync(0xffffffffu, ls1, 1);
        ls1 += __shfl_xor_sync(0xffffffffu, ls1, 2);

        // ---- cross-warp sum exchange ----
        if ((lane & 3) == 0) {
            sbuf[kh * 64 + xrow0]     = ls0;
            sbuf[kh * 64 + xrow0 + 8] = ls1;
        }
        __syncthreads();
        ls0 += sbuf[(kh ^ 1) * 64 + xrow0];
        ls1 += sbuf[(kh ^ 1) * 64 + xrow0 + 8];

        l0 = l0 * a0 + ls0; l1 = l1 * a1 + ls1;
        m0 = nm0; m1 = nm1;

#pragma unroll
        for (int i = 0; i < 32; i++) {
            out[i][0] *= a0; out[i][1] *= a0;
            out[i][2] *= a1; out[i][3] *= a1;
        }

        // ---- P frags ----
        uint32_t pah[4], pal[4];
        pksplit2(sc[0][0], sc[0][1], pah[0], pal[0]);
        pksplit2(sc[0][2], sc[0][3], pah[1], pal[1]);
        pksplit2(sc[1][0], sc[1][1], pah[2], pal[2]);
        pksplit2(sc[1][2], sc[1][3], pah[3], pal[3]);

        // ---- out += P x V^T over this warp's 16 keys ----
#pragma unroll
        for (int dp = 0; dp < 16; dp++) {
            uint32_t vh[4], vl[4];
            int rr = (dp & 7) * 16 + rb;
            uint32_t voff = (uint32_t)((dp >> 3) * 8192) + swz64(rr, kh * 2 + (lane >> 4));
            LDSM4(vh, st + 32768u + voff);
            LDSM4(vl, st + 49152u + voff);
#pragma unroll
            for (int sel = 0; sel < 2; sel++) {
                float* c = out[2 * dp + sel];
                mma16816(c, pah, vh[sel], vh[sel + 2]);
                mma16816(c, pah, vl[sel], vl[sel + 2]);
                mma16816(c, pal, vh[sel], vh[sel + 2]);
            }
        }

        MBARRIER_ARRIVE(sb + 24 + s * 8);
        if (tid == 0 && kt + 2 < nkt) {
            if (s == 0) { MBARRIER_WAIT_PARITY(sb + 24, eph0); eph0 ^= 1; }
            else        { MBARRIER_WAIT_PARITY(sb + 32, eph1); eph1 ^= 1; }
            issueKV(kt + 2, s);
        }
    }

    // ---- epilogue: cross-warp partial-out reduction, then write CTX ----
    __syncthreads();   // KV stages fully consumed; safe to reuse as reduce buffer
    const int lr0 = lane >> 2;
    if (kh == 1) {
#pragma unroll
        for (int nf = 0; nf < 32; nf++) {
            int colb = nf * 8 + (lane & 3) * 2;
            *(float2*)(red + mq * 4096 + lr0 * 256 + colb)       = make_float2(out[nf][0], out[nf][1]);
            *(float2*)(red + mq * 4096 + (lr0 + 8) * 256 + colb) = make_float2(out[nf][2], out[nf][3]);
        }
    }
    __syncthreads();
    if (kh == 0) {
        float inv0 = 1.0f / l0, inv1 = 1.0f / l1;
        float* base0 = CTX + ((size_t)(b * SEQ + row0g)) * DM + h * HDIM;
        float* base1 = CTX + ((size_t)(b * SEQ + row1g)) * DM + h * HDIM;
#pragma unroll
        for (int nf = 0; nf < 32; nf++) {
            int colb = nf * 8 + (lane & 3) * 2;
            float2 p0 = *(float2*)(red + mq * 4096 + lr0 * 256 + colb);
            float2 p1 = *(float2*)(red + mq * 4096 + (lr0 + 8) * 256 + colb);
            *(float2*)(base0 + colb) = make_float2((out[nf][0] + p0.x) * inv0,
                                                   (out[nf][1] + p0.y) * inv0);
            *(float2*)(base1 + colb) = make_float2((out[nf][2] + p1.x) * inv1,
                                                   (out[nf][3] + p1.y) * inv1);
        }
    }
}

// ---------------------------------------------------------------------------
extern "C" void kernel_launch(void* const* d_in, const int* in_sizes, int n_in,
                              void* d_out, int out_size)
{
    const float* X   = (const float*)d_in[0];
    const int*   pos = (const int*)  d_in[1];
    const float* W[4] = { (const float*)d_in[2], (const float*)d_in[3],
                          (const float*)d_in[4], (const float*)d_in[5] };
    float* out = (float*)d_out;

    float *Qg, *Kg, *Vg, *CTX;
    float2* rope;
    __nv_bfloat16 *Xhi, *Xlo, *Chi, *Clo, *WThi, *WTlo;
    __nv_bfloat16 *Qph, *Qpl, *Kph, *Kpl, *Vph, *Vpl;
    cudaGetSymbolAddress((void**)&Qg,  g_Q);
    cudaGetSymbolAddress((void**)&Kg,  g_K);
    cudaGetSymbolAddress((void**)&Vg,  g_V);
    cudaGetSymbolAddress((void**)&CTX, g_CTX);
    cudaGetSymbolAddress((void**)&rope, g_rope);
    cudaGetSymbolAddress((void**)&Xhi, g_Xhi);
    cudaGetSymbolAddress((void**)&Xlo, g_Xlo);
    cudaGetSymbolAddress((void**)&Chi, g_Chi);
    cudaGetSymbolAddress((void**)&Clo, g_Clo);
    cudaGetSymbolAddress((void**)&WThi, g_WThi);
    cudaGetSymbolAddress((void**)&WTlo, g_WTlo);
    cudaGetSymbolAddress((void**)&Qph, g_Qph);
    cudaGetSymbolAddress((void**)&Qpl, g_Qpl);
    cudaGetSymbolAddress((void**)&Kph, g_Kph);
    cudaGetSymbolAddress((void**)&Kpl, g_Kpl);
    cudaGetSymbolAddress((void**)&Vph, g_Vph);
    cudaGetSymbolAddress((void**)&Vpl, g_Vpl);

    const int GEMM_SMEM = 1024 + 1024 + 3 * 32768;             // 100352 -> 2 CTAs/SM
    const int ATTN_SMEM = 1024 + 2048 + 65536 + 2 * 65536;     // 199680
    cudaFuncSetAttribute(gemm_hmma, cudaFuncAttributeMaxDynamicSharedMemorySize, GEMM_SMEM);
    cudaFuncSetAttribute(attn_mma, cudaFuncAttributeMaxDynamicSharedMemorySize, ATTN_SMEM);

    const size_t WSZ = (size_t)DM * DM;
    dim3 trg(DM / 32, DM / 32);

    // pack GEMM operands
    rope_tab<<<(MB * SEQ * 32 + 255) / 256, 256>>>(pos, rope);
    split_rm_tiled<<<8192, 256>>>(X, Xhi, Xlo);
    for (int w = 0; w < 4; w++)
        split_tr_tiled<<<trg, 256>>>(W[w], WThi + (size_t)w * WSZ, WTlo + (size_t)w * WSZ);

    // fused QKV projection (fp32 scatter to [B,H,S,HD])
    gemm_hmma<<<dim3(96, 32), 256, GEMM_SMEM>>>(Xhi, Xlo, WThi, WTlo, Qg, Kg, Vg, 1);

    // pack attention operands (rope fused into pack_qk)
    pack_qk<<<8192, 256>>>(Qg, Kg, rope, Qph, Qpl, Kph, Kpl);
    pack_v<<<dim3(64, 32), 256>>>(Vg, Vph, Vpl);

    // attention (writes fp32 CTX)
    attn_mma<<<dim3(32, 32), 256, ATTN_SMEM>>>(Qph, Qpl, Kph, Kpl, Vph, Vpl, CTX);

    // output projection
    split_rm_tiled<<<8192, 256>>>(CTX, Chi, Clo);
    gemm_hmma<<<dim3(32, 32), 256, GEMM_SMEM>>>(Chi, Clo, WThi + 3 * WSZ, WTlo + 3 * WSZ,
                                                out, nullptr, nullptr, 0);
}